// round 12
// baseline (speedup 1.0000x reference)
#include <cuda_runtime.h>
#include <cuda_fp16.h>
#include <math.h>
#include <stdint.h>

#define Bz 4
#define Sz 1024
#define Dz 1024
#define Hz 16
#define DHz 64
#define FFz 4096
#define BSz (Bz*Sz)      // 4096
#define BHz (Bz*Hz)      // 64
#define QKVN (3*Dz)      // 3072

// ===================== scratch ==============================================
__device__ float  g_t1 [BSz*Dz];      // attn_out, then ff2 (fp32 residual)
__device__ float  g_h  [BSz*Dz];      // h (fp32)
__device__ float  g_bqkv[QKVN];       // concat bias
__device__ __half g_xh  [BSz*Dz];
__device__ __half g_qkvh[(size_t)BSz*QKVN];   // fused q|k|v, row stride 3072
__device__ __half g_vth [BSz*Dz];     // per-head V^T: [bh][d][s]
__device__ __half g_ctxh[BSz*Dz];
__device__ __half g_hh  [BSz*Dz];
__device__ __half g_ffh [BSz*FFz];
__device__ __half g_wqkvh[(size_t)QKVN*Dz];   // [3072][1024] = WqT|WkT|WvT
__device__ __half g_woh [Dz*Dz];
__device__ __half g_w1h [(size_t)Dz*FFz];
__device__ __half g_w2h [(size_t)Dz*FFz];

// ===================== helpers ==============================================
__device__ __forceinline__ uint32_t smem_u32(const void* p) {
    uint32_t a;
    asm("{ .reg .u64 t; cvta.to.shared.u64 t, %1; cvt.u32.u64 %0, t; }"
        : "=r"(a) : "l"(p));
    return a;
}
__device__ __forceinline__ void cp_async16(uint32_t dst, const void* src) {
    asm volatile("cp.async.cg.shared.global [%0], [%1], 16;"
                 :: "r"(dst), "l"(src));
}
#define CP_COMMIT() asm volatile("cp.async.commit_group;" ::: "memory")
#define CP_WAIT(n)  asm volatile("cp.async.wait_group %0;" :: "n"(n) : "memory")

__device__ __forceinline__ void ldm_x4(uint32_t* r, uint32_t addr) {
    asm volatile("ldmatrix.sync.aligned.m8n8.x4.shared.b16 {%0,%1,%2,%3}, [%4];"
                 : "=r"(r[0]), "=r"(r[1]), "=r"(r[2]), "=r"(r[3]) : "r"(addr));
}
__device__ __forceinline__ void mma_f16(float* c, const uint32_t* a,
                                        uint32_t b0, uint32_t b1) {
    asm volatile(
        "mma.sync.aligned.m16n8k16.row.col.f32.f16.f16.f32 "
        "{%0,%1,%2,%3}, {%4,%5,%6,%7}, {%8,%9}, {%0,%1,%2,%3};"
        : "+f"(c[0]), "+f"(c[1]), "+f"(c[2]), "+f"(c[3])
        : "r"(a[0]), "r"(a[1]), "r"(a[2]), "r"(a[3]), "r"(b0), "r"(b1));
}

// ===================== batched weight transpose (QKV) =======================
struct Ptr3 { const float* p[3]; };
__global__ __launch_bounds__(256) void transpose_qkv_kernel(
    Ptr3 srcs, __half* __restrict__ out)
{
    __shared__ float t[32][33];
    int z = blockIdx.z;
    const float* in = srcs.p[z];
    __half* o = out + (size_t)z * Dz * Dz;
    int c0 = blockIdx.x * 32, r0 = blockIdx.y * 32;
    int x = threadIdx.x & 31, y = threadIdx.x >> 5;
    #pragma unroll
    for (int u = 0; u < 4; u++)
        t[y + 8 * u][x] = in[(size_t)(r0 + y + 8 * u) * Dz + c0 + x];
    __syncthreads();
    #pragma unroll
    for (int u = 0; u < 4; u++)
        o[(size_t)(c0 + y + 8 * u) * Dz + r0 + x] = __float2half_rn(t[x][y + 8 * u]);
}

// ===================== generic weight transpose =============================
__global__ __launch_bounds__(256) void transpose_half_kernel(
    const float* __restrict__ in, __half* __restrict__ out, int R, int C)
{
    __shared__ float t[32][33];
    int c0 = blockIdx.x * 32, r0 = blockIdx.y * 32;
    int x = threadIdx.x & 31, y = threadIdx.x >> 5;
    #pragma unroll
    for (int u = 0; u < 4; u++)
        t[y + 8 * u][x] = in[(size_t)(r0 + y + 8 * u) * C + c0 + x];
    __syncthreads();
    #pragma unroll
    for (int u = 0; u < 4; u++)
        out[(size_t)(c0 + y + 8 * u) * R + r0 + x] = __float2half_rn(t[x][y + 8 * u]);
}

// ===================== bias concat ==========================================
__global__ __launch_bounds__(256) void bias_concat_kernel(
    const float* __restrict__ bq, const float* __restrict__ bk,
    const float* __restrict__ bv, float* __restrict__ o)
{
    int i = blockIdx.x * 256 + threadIdx.x;
    float v = (i < Dz) ? bq[i] : (i < 2 * Dz) ? bk[i - Dz] : bv[i - 2 * Dz];
    o[i] = v;
}

// ===================== cvt copy: out_h = half(in) ===========================
__global__ __launch_bounds__(256) void cvt_half_kernel(
    const float* __restrict__ in, __half* __restrict__ out)
{
    size_t i = ((size_t)blockIdx.x * 256 + threadIdx.x) * 4;
    float4 v = *(const float4*)(in + i);
    __half2* o = (__half2*)(out + i);
    o[0] = __floats2half2_rn(v.x, v.y);
    o[1] = __floats2half2_rn(v.z, v.w);
}

// ===================== per-head V transpose (strided src) ===================
__global__ __launch_bounds__(256) void vtrans_kernel(
    const __half* __restrict__ v, int ldv, __half* __restrict__ vt)
{
    __shared__ __half t[32][34];
    int s0 = blockIdx.x * 32, d0 = blockIdx.y * 32, bh = blockIdx.z;
    int b = bh / Hz, h = bh % Hz;
    int x = threadIdx.x & 31, y = threadIdx.x >> 5;
    #pragma unroll
    for (int u = 0; u < 4; u++)
        t[y + 8 * u][x] = v[(size_t)(b * Sz + s0 + y + 8 * u) * ldv + h * DHz + d0 + x];
    __syncthreads();
    #pragma unroll
    for (int u = 0; u < 4; u++)
        vt[((size_t)bh * DHz + d0 + y + 8 * u) * Sz + s0 + x] = t[x][y + 8 * u];
}

// ===================== FP16 mma GEMM: 128x128x64, 256 thr, 2 CTAs/SM ========
// 8 warps (2m x 4n), warp tile 64x32, 3-stage cp.async, ONE barrier/chunk.
// Two independent CTAs per SM interleave across barriers.
#define GBM 128
#define GBN 128
#define GBK 64
#define KST2 72                          // smem row stride (halfs)
#define STG_A 18432                      // 128*72*2
#define STG_BYTES 36864                  // A + B (each 128 rows x 72)
#define NSTAGE 3
#define GEMM_SMEM (NSTAGE * STG_BYTES)   // 110592

__global__ __launch_bounds__(256, 2) void hgemm_kernel(
    const __half* __restrict__ A, const __half* __restrict__ Bt,
    const float* __restrict__ bias, float* __restrict__ Cf,
    __half* __restrict__ Ch, int M, int N, int K, int relu)
{
    extern __shared__ __half hsm[];
    uint32_t sbase = smem_u32(hsm);
    int tid = threadIdx.x;
    int wid = tid >> 5, lane = tid & 31;
    int m0 = blockIdx.y * GBM, n0 = blockIdx.x * GBN;
    int warp_m = wid >> 2, warp_n = wid & 3;     // 2 x 4
    int lg = lane >> 2, lq = lane & 3;

    float acc[4][4][4] = {};

    // cp.async mapping: row = tid>>1 (0..127), seg = (tid&1)*32 halfs (4x16B)
    int arow = tid >> 1, acol = (tid & 1) * 32;
    uint32_t offA = (uint32_t)(arow * KST2 + acol) * 2;
    const __half* Ap = A  + (size_t)(m0 + arow) * K + acol;
    const __half* Bp = Bt + (size_t)(n0 + arow) * K + acol;

    const int nchunks = K / GBK;

    #pragma unroll
    for (int pc = 0; pc < 2; pc++) {
        uint32_t base = sbase + (uint32_t)pc * STG_BYTES;
        size_t koff = (size_t)pc * GBK;
        const __half* Ac = Ap + koff;
        const __half* Bc = Bp + koff;
        #pragma unroll
        for (int u = 0; u < 4; u++) {
            cp_async16(base + offA + u * 16,         Ac + u * 8);
            cp_async16(base + STG_A + offA + u * 16, Bc + u * 8);
        }
        CP_COMMIT();
    }

    int a_row_off = (lane & 7) + ((lane & 8) ? 8 : 0);
    int a_col_off = (lane & 16) ? 8 : 0;
    int b_row_off = (lane & 7) + ((lane & 16) ? 8 : 0);
    int b_col_off = (lane & 8) ? 8 : 0;

    for (int c = 0; c < nchunks; c++) {
        CP_WAIT(1);
        __syncthreads();

        if (c + 2 < nchunks) {
            uint32_t base = sbase + (uint32_t)((c + 2) % NSTAGE) * STG_BYTES;
            size_t koff = (size_t)(c + 2) * GBK;
            const __half* Ac = Ap + koff;
            const __half* Bc = Bp + koff;
            #pragma unroll
            for (int u = 0; u < 4; u++) {
                cp_async16(base + offA + u * 16,         Ac + u * 8);
                cp_async16(base + STG_A + offA + u * 16, Bc + u * 8);
            }
        }
        CP_COMMIT();

        uint32_t abase = sbase + (uint32_t)(c % NSTAGE) * STG_BYTES;
        uint32_t bbase = abase + STG_A;

        #pragma unroll
        for (int ks = 0; ks < 4; ks++) {
            int kc = ks * 16;
            uint32_t af[4][4];
            #pragma unroll
            for (int im = 0; im < 4; im++) {
                int row = warp_m * 64 + im * 16 + a_row_off;
                ldm_x4(af[im], abase + (uint32_t)(row * KST2 + kc + a_col_off) * 2);
            }
            uint32_t bf[2][4];
            #pragma unroll
            for (int pr = 0; pr < 2; pr++) {
                int row = warp_n * 32 + pr * 16 + b_row_off;
                ldm_x4(bf[pr], bbase + (uint32_t)(row * KST2 + kc + b_col_off) * 2);
            }
            #pragma unroll
            for (int im = 0; im < 4; im++)
                #pragma unroll
                for (int pr = 0; pr < 2; pr++) {
                    mma_f16(acc[im][pr * 2 + 0], af[im], bf[pr][0], bf[pr][1]);
                    mma_f16(acc[im][pr * 2 + 1], af[im], bf[pr][2], bf[pr][3]);
                }
        }
    }

    // epilogue: warp writes 64x32
    #pragma unroll
    for (int im = 0; im < 4; im++) {
        int r0 = m0 + warp_m * 64 + im * 16 + lg;
        #pragma unroll
        for (int nt = 0; nt < 4; nt++) {
            int cc = n0 + warp_n * 32 + nt * 8 + 2 * lq;
            float b0 = bias[cc], b1 = bias[cc + 1];
            float v00 = acc[im][nt][0] + b0, v01 = acc[im][nt][1] + b1;
            float v10 = acc[im][nt][2] + b0, v11 = acc[im][nt][3] + b1;
            if (relu) {
                v00 = fmaxf(v00, 0.f); v01 = fmaxf(v01, 0.f);
                v10 = fmaxf(v10, 0.f); v11 = fmaxf(v11, 0.f);
            }
            if (Cf) {
                float2 a2; a2.x = v00; a2.y = v01;
                float2 b2; b2.x = v10; b2.y = v11;
                *(float2*)(Cf + (size_t)r0 * N + cc) = a2;
                *(float2*)(Cf + (size_t)(r0 + 8) * N + cc) = b2;
            }
            if (Ch) {
                *(__half2*)(Ch + (size_t)r0 * N + cc) = __floats2half2_rn(v00, v01);
                *(__half2*)(Ch + (size_t)(r0 + 8) * N + cc) = __floats2half2_rn(v10, v11);
            }
        }
    }
}

// ===================== fused attention ======================================
#define SST 72           // Q/K/V tile row stride (halfs)
#define PST 1032         // P row stride in halfs (2064B; %128=16 -> no conflicts)
#define ATT_SMEM 161024

__global__ __launch_bounds__(256) void attn_fused_kernel(
    const __half* __restrict__ Q, const __half* __restrict__ Kb, int ldqk,
    const __half* __restrict__ vt, float* __restrict__ attn,
    __half* __restrict__ ctxh)
{
    extern __shared__ char asmem[];
    __half* Qs = (__half*)asmem;              // 64*SST
    __half* Ks = Qs + 64 * SST;               // 2 buffers of 64*SST
    __half* Ps = Ks + 2 * 64 * SST;           // 64*PST
    float* red  = (float*)(Ps + 64 * PST);    // [4][64]
    float* linv = red + 256;                  // [64]
    uint32_t qb  = smem_u32(Qs);
    uint32_t kb0 = smem_u32(Ks);
    uint32_t pb  = smem_u32(Ps);

    int it = 15 - (int)blockIdx.x;            // longest blocks first
    int bh = blockIdx.y;
    int b = bh / Hz, h = bh % Hz;
    int tid = threadIdx.x, wid = tid >> 5, lane = tid & 31;
    int lg = lane >> 2, lq = lane & 3;
    int warp_m = wid >> 2, warp_n = wid & 3;
    int a_row_off = (lane & 7) + ((lane & 8) ? 8 : 0);
    int a_col_off = (lane & 16) ? 8 : 0;
    int b_row_off = (lane & 7) + ((lane & 16) ? 8 : 0);
    int b_col_off = (lane & 8) ? 8 : 0;

    #pragma unroll
    for (int u = 0; u < 2; u++) {
        int s = tid + u * 256;
        int row = s >> 3, col = (s & 7) * 8;
        cp_async16(qb + (uint32_t)(row * SST + col) * 2,
                   Q + (size_t)(b * Sz + it * 64 + row) * ldqk + h * DHz + col);
    }
    CP_COMMIT();
    #pragma unroll
    for (int u = 0; u < 2; u++) {
        int s = tid + u * 256;
        int row = s >> 3, col = (s & 7) * 8;
        cp_async16(kb0 + (uint32_t)(row * SST + col) * 2,
                   Kb + (size_t)(b * Sz + row) * ldqk + h * DHz + col);
    }
    CP_COMMIT();

    float psum[2][2] = {};

    // ---------------- pass 1: S, exp, P -> smem ----------------
    for (int kt = 0; kt <= it; kt++) {
        CP_WAIT(0);
        __syncthreads();
        if (kt < it) {
            uint32_t nb = kb0 + (uint32_t)(((kt + 1) & 1) * 64 * SST * 2);
            #pragma unroll
            for (int u = 0; u < 2; u++) {
                int s = tid + u * 256;
                int row = s >> 3, col = (s & 7) * 8;
                cp_async16(nb + (uint32_t)(row * SST + col) * 2,
                           Kb + (size_t)(b * Sz + (kt + 1) * 64 + row) * ldqk
                               + h * DHz + col);
            }
            CP_COMMIT();
        }
        uint32_t kb = kb0 + (uint32_t)((kt & 1) * 64 * SST * 2);

        float accS[2][2][4] = {};
        #pragma unroll
        for (int ks = 0; ks < 4; ks++) {
            int kc = ks * 16;
            uint32_t af[2][4];
            #pragma unroll
            for (int im = 0; im < 2; im++) {
                int row = warp_m * 32 + im * 16 + a_row_off;
                ldm_x4(af[im], qb + (uint32_t)(row * SST + kc + a_col_off) * 2);
            }
            uint32_t bf[4];
            {
                int row = warp_n * 16 + b_row_off;
                ldm_x4(bf, kb + (uint32_t)(row * SST + kc + b_col_off) * 2);
            }
            #pragma unroll
            for (int im = 0; im < 2; im++) {
                mma_f16(accS[im][0], af[im], bf[0], bf[1]);
                mma_f16(accS[im][1], af[im], bf[2], bf[3]);
            }
        }

        int diag = (kt == it);
        #pragma unroll
        for (int im = 0; im < 2; im++) {
            int r0 = warp_m * 32 + im * 16 + lg;
            int g0 = it * 64 + r0, g1 = g0 + 8;
            #pragma unroll
            for (int nt = 0; nt < 2; nt++) {
                int gc = kt * 64 + warp_n * 16 + nt * 8 + 2 * lq;
                float p00 = __expf(accS[im][nt][0] * 0.125f);
                float p01 = __expf(accS[im][nt][1] * 0.125f);
                float p10 = __expf(accS[im][nt][2] * 0.125f);
                float p11 = __expf(accS[im][nt][3] * 0.125f);
                if (diag) {
                    if (gc     > g0) p00 = 0.f;
                    if (gc + 1 > g0) p01 = 0.f;
                    if (gc     > g1) p10 = 0.f;
                    if (gc + 1 > g1) p11 = 0.f;
                }
                psum[im][0] += p00 + p01;
                psum[im][1] += p10 + p11;
                *(__half2*)&Ps[r0 * PST + gc]       = __floats2half2_rn(p00, p01);
                *(__half2*)&Ps[(r0 + 8) * PST + gc] = __floats2half2_rn(p10, p11);
            }
        }
    }

    __syncthreads();

    // prefetch V[0]
    #pragma unroll
    for (int u = 0; u < 2; u++) {
        int s = tid + u * 256;
        int row = s >> 3, col = (s & 7) * 8;
        cp_async16(kb0 + (uint32_t)(row * SST + col) * 2,
                   vt + ((size_t)bh * DHz + row) * Sz + col);
    }
    CP_COMMIT();

    // row-sum reduce -> linv
    #pragma unroll
    for (int im = 0; im < 2; im++)
        #pragma unroll
        for (int rh = 0; rh < 2; rh++) {
            float v = psum[im][rh];
            v += __shfl_xor_sync(0xffffffff, v, 1);
            v += __shfl_xor_sync(0xffffffff, v, 2);
            if (lq == 0) {
                int row = warp_m * 32 + im * 16 + lg + rh * 8;
                red[warp_n * 64 + row] = v;
            }
        }
    __syncthreads();
    if (tid < 64) {
        float l = red[tid] + red[64 + tid] + red[128 + tid] + red[192 + tid];
        linv[tid] = 1.f / l;
    }
    __syncthreads();

    // ---------------- pass 2: O = P @ V ----------------
    float accO[2][2][4] = {};
    for (int kt = 0; kt <= it; kt++) {
        CP_WAIT(0);
        __syncthreads();
        if (kt < it) {
            uint32_t nb = kb0 + (uint32_t)(((kt + 1) & 1) * 64 * SST * 2);
            #pragma unroll
            for (int u = 0; u < 2; u++) {
                int s = tid + u * 256;
                int row = s >> 3, col = (s & 7) * 8;
                cp_async16(nb + (uint32_t)(row * SST + col) * 2,
                           vt + ((size_t)bh * DHz + row) * Sz + (kt + 1) * 64 + col);
            }
            CP_COMMIT();
        }
        uint32_t vb = kb0 + (uint32_t)((kt & 1) * 64 * SST * 2);

        #pragma unroll
        for (int ks = 0; ks < 4; ks++) {
            int kc = kt * 64 + ks * 16;
            uint32_t af[2][4];
            #pragma unroll
            for (int im = 0; im < 2; im++) {
                int row = warp_m * 32 + im * 16 + a_row_off;
                ldm_x4(af[im], pb + (uint32_t)(row * PST + kc + a_col_off) * 2);
            }
            uint32_t bf[4];
            {
                int row = warp_n * 16 + b_row_off;
                ldm_x4(bf, vb + (uint32_t)(row * SST + ks * 16 + b_col_off) * 2);
            }
            #pragma unroll
            for (int im = 0; im < 2; im++) {
                mma_f16(accO[im][0], af[im], bf[0], bf[1]);
                mma_f16(accO[im][1], af[im], bf[2], bf[3]);
            }
        }
    }

    // ctx write (normalized)
    #pragma unroll
    for (int im = 0; im < 2; im++) {
        int r0 = warp_m * 32 + im * 16 + lg;
        float il0 = linv[r0], il1 = linv[r0 + 8];
        int gr = it * 64 + r0;
        #pragma unroll
        for (int nt = 0; nt < 2; nt++) {
            int d = warp_n * 16 + nt * 8 + 2 * lq;
            __half* p0 = ctxh + ((size_t)(b * Sz) + gr) * Dz + h * DHz + d;
            __half* p1 = p0 + (size_t)8 * Dz;
            *(__half2*)p0 = __floats2half2_rn(accO[im][nt][0] * il0,
                                              accO[im][nt][1] * il0);
            *(__half2*)p1 = __floats2half2_rn(accO[im][nt][2] * il1,
                                              accO[im][nt][3] * il1);
        }
    }

    // attn write
    for (int j = 0; j < 64; j++) {
        int grow = it * 64 + j;
        int limit = grow + 1;
        float il = linv[j];
        int col = tid * 4;
        float4 o;
        o.x = (col     < limit) ? __half2float(Ps[j * PST + col])     * il : 0.f;
        o.y = (col + 1 < limit) ? __half2float(Ps[j * PST + col + 1]) * il : 0.f;
        o.z = (col + 2 < limit) ? __half2float(Ps[j * PST + col + 2]) * il : 0.f;
        o.w = (col + 3 < limit) ? __half2float(Ps[j * PST + col + 3]) * il : 0.f;
        *(float4*)(attn + ((size_t)bh * Sz + grow) * Sz + col) = o;
    }
}

// ===================== residual + LayerNorm (fp32, optional half out) =======
__global__ __launch_bounds__(256) void add_ln_kernel(
    const float* __restrict__ x, const float* __restrict__ r,
    const float* __restrict__ g, const float* __restrict__ be,
    float* __restrict__ out, __half* __restrict__ outh)
{
    int row = blockIdx.x;
    const float* xr = x + (size_t)row * Dz;
    const float* rr = r + (size_t)row * Dz;
    float* orow = out + (size_t)row * Dz;
    int tid = threadIdx.x;

    float v[4];
    float lsum = 0.f, lsq = 0.f;
    #pragma unroll
    for (int u = 0; u < 4; u++) {
        int c = tid + u * 256;
        v[u] = xr[c] + rr[c];
        lsum += v[u];
        lsq  += v[u] * v[u];
    }

    __shared__ float s1[256], s2[256];
    s1[tid] = lsum; s2[tid] = lsq;
    __syncthreads();
    #pragma unroll
    for (int s = 128; s > 0; s >>= 1) {
        if (tid < s) { s1[tid] += s1[tid + s]; s2[tid] += s2[tid + s]; }
        __syncthreads();
    }
    float mean = s1[0] * (1.f / Dz);
    float var  = s2[0] * (1.f / Dz) - mean * mean;
    float inv  = rsqrtf(var + 1e-5f);

    #pragma unroll
    for (int u = 0; u < 4; u++) {
        int c = tid + u * 256;
        float o = (v[u] - mean) * inv * g[c] + be[c];
        orow[c] = o;
        if (outh) outh[(size_t)row * Dz + c] = __float2half_rn(o);
    }
}

// ===================== host launch ==========================================
extern "C" void kernel_launch(void* const* d_in, const int* in_sizes, int n_in,
                              void* d_out, int out_size)
{
    const float* x    = (const float*)d_in[0];
    const float* Wq   = (const float*)d_in[1];
    const float* bq   = (const float*)d_in[2];
    const float* Wk   = (const float*)d_in[3];
    const float* bk   = (const float*)d_in[4];
    const float* Wv   = (const float*)d_in[5];
    const float* bv   = (const float*)d_in[6];
    const float* Wo   = (const float*)d_in[7];
    const float* bo   = (const float*)d_in[8];
    const float* ln1g = (const float*)d_in[9];
    const float* ln1b = (const float*)d_in[10];
    const float* W1   = (const float*)d_in[11];
    const float* b1   = (const float*)d_in[12];
    const float* W2   = (const float*)d_in[13];
    const float* b2   = (const float*)d_in[14];
    const float* ln2g = (const float*)d_in[15];
    const float* ln2b = (const float*)d_in[16];

    float* out  = (float*)d_out;
    float* y    = out;
    float* attn = out + (size_t)BSz * Dz;

    float *t1, *h, *bqkv;
    __half *xh, *qkvh, *vth, *ctxh, *hh, *ffh;
    __half *wqkvh, *woh, *w1h, *w2h;
    cudaGetSymbolAddress((void**)&t1,   g_t1);
    cudaGetSymbolAddress((void**)&h,    g_h);
    cudaGetSymbolAddress((void**)&bqkv, g_bqkv);
    cudaGetSymbolAddress((void**)&xh,   g_xh);
    cudaGetSymbolAddress((void**)&qkvh, g_qkvh);
    cudaGetSymbolAddress((void**)&vth,  g_vth);
    cudaGetSymbolAddress((void**)&ctxh, g_ctxh);
    cudaGetSymbolAddress((void**)&hh,   g_hh);
    cudaGetSymbolAddress((void**)&ffh,  g_ffh);
    cudaGetSymbolAddress((void**)&wqkvh, g_wqkvh);
    cudaGetSymbolAddress((void**)&woh,  g_woh);
    cudaGetSymbolAddress((void**)&w1h,  g_w1h);
    cudaGetSymbolAddress((void**)&w2h,  g_w2h);

    cudaFuncSetAttribute(hgemm_kernel,
                         cudaFuncAttributeMaxDynamicSharedMemorySize, GEMM_SMEM);
    cudaFuncSetAttribute(attn_fused_kernel,
                         cudaFuncAttributeMaxDynamicSharedMemorySize, ATT_SMEM);

    const __half* qh = qkvh;
    const __half* kh = qkvh + Dz;
    const __half* vh = qkvh + 2 * Dz;

    dim3 tDD(Dz / 32, Dz / 32);
    dim3 gQKV(QKVN / GBN, BSz / GBM);   // 24 x 32 = 768 CTAs
    dim3 gDD(Dz / GBN, BSz / GBM);      // 8 x 32 = 256 CTAs
    dim3 gDF(FFz / GBN, BSz / GBM);     // 32 x 32 = 1024 CTAs

    Ptr3 wsrc; wsrc.p[0] = Wq; wsrc.p[1] = Wk; wsrc.p[2] = Wv;

    cvt_half_kernel<<<(BSz * Dz) / 1024, 256>>>(x, xh);                       // 0
    transpose_qkv_kernel<<<dim3(Dz / 32, Dz / 32, 3), 256>>>(wsrc, wqkvh);    // 1
    bias_concat_kernel<<<QKVN / 256, 256>>>(bq, bk, bv, bqkv);                // 2
    hgemm_kernel<<<gQKV, 256, GEMM_SMEM>>>(xh, wqkvh, bqkv, nullptr, qkvh,
                                           BSz, QKVN, Dz, 0);                 // 3
    transpose_half_kernel<<<dim3(FFz / 32, Dz / 32), 256>>>(W1, w1h, Dz, FFz);// 4
    vtrans_kernel<<<dim3(Sz / 32, DHz / 32, BHz), 256>>>(vh, QKVN, vth);      // 5

    attn_fused_kernel<<<dim3(Sz / 64, BHz), 256, ATT_SMEM>>>(
        qh, kh, QKVN, vth, attn, ctxh);                                       // 6

    transpose_half_kernel<<<tDD, 256>>>(Wo, woh, Dz, Dz);                     // 7
    hgemm_kernel<<<gDD, 256, GEMM_SMEM>>>(ctxh, woh, bo, t1, nullptr,
                                          BSz, Dz, Dz, 0);                    // 8
    add_ln_kernel<<<BSz, 256>>>(x, t1, ln1g, ln1b, h, hh);                    // 9
    transpose_half_kernel<<<dim3(Dz / 32, FFz / 32), 256>>>(W2, w2h, FFz, Dz);// 10
    hgemm_kernel<<<gDF, 256, GEMM_SMEM>>>(hh, w1h, b1, nullptr, ffh,
                                          BSz, FFz, Dz, 1);                   // 11
    hgemm_kernel<<<gDD, 256, GEMM_SMEM>>>(ffh, w2h, b2, t1, nullptr,
                                          BSz, Dz, FFz, 0);                   // 12
    add_ln_kernel<<<BSz, 256>>>(h, t1, ln2g, ln2b, y, nullptr);               // 13
}

// round 13
// speedup vs baseline: 1.2400x; 1.2400x over previous
#include <cuda_runtime.h>
#include <cuda_fp16.h>
#include <math.h>
#include <stdint.h>

#define Bz 4
#define Sz 1024
#define Dz 1024
#define Hz 16
#define DHz 64
#define FFz 4096
#define BSz (Bz*Sz)      // 4096
#define BHz (Bz*Hz)      // 64
#define QKVN (3*Dz)      // 3072

// ===================== scratch ==============================================
__device__ float  g_t1 [BSz*Dz];      // attn_out, then ff2 (fp32 residual)
__device__ float  g_h  [BSz*Dz];      // h (fp32)
__device__ float  g_bqkv[QKVN];       // concat bias
__device__ __half g_xh  [BSz*Dz];
__device__ __half g_qkvh[(size_t)BSz*QKVN];   // fused q|k|v, row stride 3072
__device__ __half g_ctxh[BSz*Dz];
__device__ __half g_hh  [BSz*Dz];
__device__ __half g_ffh [BSz*FFz];
__device__ __half g_wqkvh[(size_t)QKVN*Dz];   // [3072][1024] = WqT|WkT|WvT
__device__ __half g_woh [Dz*Dz];
__device__ __half g_w1h [(size_t)Dz*FFz];
__device__ __half g_w2h [(size_t)Dz*FFz];

// ===================== helpers ==============================================
__device__ __forceinline__ uint32_t smem_u32(const void* p) {
    uint32_t a;
    asm("{ .reg .u64 t; cvta.to.shared.u64 t, %1; cvt.u32.u64 %0, t; }"
        : "=r"(a) : "l"(p));
    return a;
}
__device__ __forceinline__ void cp_async16(uint32_t dst, const void* src) {
    asm volatile("cp.async.cg.shared.global [%0], [%1], 16;"
                 :: "r"(dst), "l"(src));
}
#define CP_COMMIT() asm volatile("cp.async.commit_group;" ::: "memory")
#define CP_WAIT(n)  asm volatile("cp.async.wait_group %0;" :: "n"(n) : "memory")

__device__ __forceinline__ void ldm_x4(uint32_t* r, uint32_t addr) {
    asm volatile("ldmatrix.sync.aligned.m8n8.x4.shared.b16 {%0,%1,%2,%3}, [%4];"
                 : "=r"(r[0]), "=r"(r[1]), "=r"(r[2]), "=r"(r[3]) : "r"(addr));
}
__device__ __forceinline__ void ldm_x4_trans(uint32_t* r, uint32_t addr) {
    asm volatile("ldmatrix.sync.aligned.m8n8.x4.trans.shared.b16 {%0,%1,%2,%3}, [%4];"
                 : "=r"(r[0]), "=r"(r[1]), "=r"(r[2]), "=r"(r[3]) : "r"(addr));
}
__device__ __forceinline__ void mma_f16(float* c, const uint32_t* a,
                                        uint32_t b0, uint32_t b1) {
    asm volatile(
        "mma.sync.aligned.m16n8k16.row.col.f32.f16.f16.f32 "
        "{%0,%1,%2,%3}, {%4,%5,%6,%7}, {%8,%9}, {%0,%1,%2,%3};"
        : "+f"(c[0]), "+f"(c[1]), "+f"(c[2]), "+f"(c[3])
        : "r"(a[0]), "r"(a[1]), "r"(a[2]), "r"(a[3]), "r"(b0), "r"(b1));
}

// ===================== batched weight transpose (QKV) =======================
struct Ptr3 { const float* p[3]; };
__global__ __launch_bounds__(256) void transpose_qkv_kernel(
    Ptr3 srcs, __half* __restrict__ out)
{
    __shared__ float t[32][33];
    int z = blockIdx.z;
    const float* in = srcs.p[z];
    __half* o = out + (size_t)z * Dz * Dz;
    int c0 = blockIdx.x * 32, r0 = blockIdx.y * 32;
    int x = threadIdx.x & 31, y = threadIdx.x >> 5;
    #pragma unroll
    for (int u = 0; u < 4; u++)
        t[y + 8 * u][x] = in[(size_t)(r0 + y + 8 * u) * Dz + c0 + x];
    __syncthreads();
    #pragma unroll
    for (int u = 0; u < 4; u++)
        o[(size_t)(c0 + y + 8 * u) * Dz + r0 + x] = __float2half_rn(t[x][y + 8 * u]);
}

// ===================== generic weight transpose =============================
__global__ __launch_bounds__(256) void transpose_half_kernel(
    const float* __restrict__ in, __half* __restrict__ out, int R, int C)
{
    __shared__ float t[32][33];
    int c0 = blockIdx.x * 32, r0 = blockIdx.y * 32;
    int x = threadIdx.x & 31, y = threadIdx.x >> 5;
    #pragma unroll
    for (int u = 0; u < 4; u++)
        t[y + 8 * u][x] = in[(size_t)(r0 + y + 8 * u) * C + c0 + x];
    __syncthreads();
    #pragma unroll
    for (int u = 0; u < 4; u++)
        out[(size_t)(c0 + y + 8 * u) * R + r0 + x] = __float2half_rn(t[x][y + 8 * u]);
}

// ===================== bias concat ==========================================
__global__ __launch_bounds__(256) void bias_concat_kernel(
    const float* __restrict__ bq, const float* __restrict__ bk,
    const float* __restrict__ bv, float* __restrict__ o)
{
    int i = blockIdx.x * 256 + threadIdx.x;
    float v = (i < Dz) ? bq[i] : (i < 2 * Dz) ? bk[i - Dz] : bv[i - 2 * Dz];
    o[i] = v;
}

// ===================== cvt copy: out_h = half(in) ===========================
__global__ __launch_bounds__(256) void cvt_half_kernel(
    const float* __restrict__ in, __half* __restrict__ out)
{
    size_t i = ((size_t)blockIdx.x * 256 + threadIdx.x) * 4;
    float4 v = *(const float4*)(in + i);
    __half2* o = (__half2*)(out + i);
    o[0] = __floats2half2_rn(v.x, v.y);
    o[1] = __floats2half2_rn(v.z, v.w);
}

// ===================== FP16 mma GEMM: 128x256x64, 512 thr, 3-stage ==========
// 16 warps (2m x 8n), warp tile 64x32. ONE __syncthreads per k-chunk.
#define GBM 128
#define GBN 256
#define GBK 64
#define KST2 72
#define STG_A 18432
#define STG_BYTES 55296
#define NSTAGE 3
#define GEMM_SMEM (NSTAGE * STG_BYTES)   // 165888

__global__ __launch_bounds__(512) void hgemm_kernel(
    const __half* __restrict__ A, const __half* __restrict__ Bt,
    const float* __restrict__ bias, float* __restrict__ Cf,
    __half* __restrict__ Ch, int M, int N, int K, int relu)
{
    extern __shared__ __half hsm[];
    uint32_t sbase = smem_u32(hsm);
    int tid = threadIdx.x;
    int wid = tid >> 5, lane = tid & 31;
    int m0 = blockIdx.y * GBM, n0 = blockIdx.x * GBN;
    int warp_m = wid >> 3, warp_n = wid & 7;
    int lg = lane >> 2, lq = lane & 3;

    float acc[4][4][4] = {};

    int row0 = tid >> 3, col0 = (tid & 7) * 8;
    uint32_t offA = (uint32_t)(row0 * KST2 + col0) * 2;
    const __half* Ap = A  + (size_t)(m0 + row0) * K + col0;
    const __half* Bp = Bt + (size_t)(n0 + row0) * K + col0;
    const size_t K64 = (size_t)64 * K;

    const int nchunks = K / GBK;

    #pragma unroll
    for (int pc = 0; pc < 2; pc++) {
        uint32_t base = sbase + (uint32_t)pc * STG_BYTES;
        size_t koff = (size_t)pc * GBK;
        cp_async16(base + offA,                 Ap + koff);
        cp_async16(base + offA + 64*KST2*2,     Ap + koff + K64);
        uint32_t bb = base + STG_A + offA;
        cp_async16(bb,                  Bp + koff);
        cp_async16(bb + 64*KST2*2,      Bp + koff + K64);
        cp_async16(bb + 128*KST2*2,     Bp + koff + 2*K64);
        cp_async16(bb + 192*KST2*2,     Bp + koff + 3*K64);
        CP_COMMIT();
    }

    int a_row_off = (lane & 7) + ((lane & 8) ? 8 : 0);
    int a_col_off = (lane & 16) ? 8 : 0;
    int b_row_off = (lane & 7) + ((lane & 16) ? 8 : 0);
    int b_col_off = (lane & 8) ? 8 : 0;

    for (int c = 0; c < nchunks; c++) {
        CP_WAIT(1);
        __syncthreads();

        if (c + 2 < nchunks) {
            uint32_t base = sbase + (uint32_t)((c + 2) % NSTAGE) * STG_BYTES;
            size_t koff = (size_t)(c + 2) * GBK;
            cp_async16(base + offA,                 Ap + koff);
            cp_async16(base + offA + 64*KST2*2,     Ap + koff + K64);
            uint32_t bb = base + STG_A + offA;
            cp_async16(bb,                  Bp + koff);
            cp_async16(bb + 64*KST2*2,      Bp + koff + K64);
            cp_async16(bb + 128*KST2*2,     Bp + koff + 2*K64);
            cp_async16(bb + 192*KST2*2,     Bp + koff + 3*K64);
        }
        CP_COMMIT();

        uint32_t abase = sbase + (uint32_t)(c % NSTAGE) * STG_BYTES;
        uint32_t bbase = abase + STG_A;

        #pragma unroll
        for (int ks = 0; ks < 4; ks++) {
            int kc = ks * 16;
            uint32_t af[4][4];
            #pragma unroll
            for (int im = 0; im < 4; im++) {
                int row = warp_m * 64 + im * 16 + a_row_off;
                ldm_x4(af[im], abase + (uint32_t)(row * KST2 + kc + a_col_off) * 2);
            }
            uint32_t bf[2][4];
            #pragma unroll
            for (int pr = 0; pr < 2; pr++) {
                int row = warp_n * 32 + pr * 16 + b_row_off;
                ldm_x4(bf[pr], bbase + (uint32_t)(row * KST2 + kc + b_col_off) * 2);
            }
            #pragma unroll
            for (int im = 0; im < 4; im++)
                #pragma unroll
                for (int pr = 0; pr < 2; pr++) {
                    mma_f16(acc[im][pr * 2 + 0], af[im], bf[pr][0], bf[pr][1]);
                    mma_f16(acc[im][pr * 2 + 1], af[im], bf[pr][2], bf[pr][3]);
                }
        }
    }

    #pragma unroll
    for (int im = 0; im < 4; im++) {
        int r0 = m0 + warp_m * 64 + im * 16 + lg;
        #pragma unroll
        for (int nt = 0; nt < 4; nt++) {
            int cc = n0 + warp_n * 32 + nt * 8 + 2 * lq;
            float b0 = bias[cc], b1 = bias[cc + 1];
            float v00 = acc[im][nt][0] + b0, v01 = acc[im][nt][1] + b1;
            float v10 = acc[im][nt][2] + b0, v11 = acc[im][nt][3] + b1;
            if (relu) {
                v00 = fmaxf(v00, 0.f); v01 = fmaxf(v01, 0.f);
                v10 = fmaxf(v10, 0.f); v11 = fmaxf(v11, 0.f);
            }
            if (Cf) {
                float2 a2; a2.x = v00; a2.y = v01;
                float2 b2; b2.x = v10; b2.y = v11;
                *(float2*)(Cf + (size_t)r0 * N + cc) = a2;
                *(float2*)(Cf + (size_t)(r0 + 8) * N + cc) = b2;
            }
            if (Ch) {
                *(__half2*)(Ch + (size_t)r0 * N + cc) = __floats2half2_rn(v00, v01);
                *(__half2*)(Ch + (size_t)(r0 + 8) * N + cc) = __floats2half2_rn(v10, v11);
            }
        }
    }
}

// ===================== fused attention ======================================
// V tiles loaded directly from qkvh ([s][d] layout) — P@V B-fragments come
// from ldmatrix.x4.trans (mapping validated in R11). No separate V^T pass.
#define SST 72           // Q/K/V tile row stride (halfs)
#define PST 1032         // P row stride in halfs (2064B; %128=16 -> no conflicts)
#define ATT_SMEM 161024

__global__ __launch_bounds__(256) void attn_fused_kernel(
    const __half* __restrict__ Q, const __half* __restrict__ Kb,
    const __half* __restrict__ V, int ldqk,
    float* __restrict__ attn, __half* __restrict__ ctxh)
{
    extern __shared__ char asmem[];
    __half* Qs = (__half*)asmem;              // 64*SST
    __half* Ks = Qs + 64 * SST;               // 2 buffers of 64*SST
    __half* Ps = Ks + 2 * 64 * SST;           // 64*PST
    float* red  = (float*)(Ps + 64 * PST);    // [4][64]
    float* linv = red + 256;                  // [64]
    uint32_t qb  = smem_u32(Qs);
    uint32_t kb0 = smem_u32(Ks);
    uint32_t pb  = smem_u32(Ps);

    int it = 15 - (int)blockIdx.x;            // longest blocks first
    int bh = blockIdx.y;
    int b = bh / Hz, h = bh % Hz;
    int tid = threadIdx.x, wid = tid >> 5, lane = tid & 31;
    int lg = lane >> 2, lq = lane & 3;
    int warp_m = wid >> 2, warp_n = wid & 3;
    int a_row_off = (lane & 7) + ((lane & 8) ? 8 : 0);
    int a_col_off = (lane & 16) ? 8 : 0;
    int b_row_off = (lane & 7) + ((lane & 16) ? 8 : 0);
    int b_col_off = (lane & 8) ? 8 : 0;
    // trans-B (V) lane addressing: row = k (s), col = n (d)
    int bt_row_off = (lane & 7) + ((lane & 8) ? 8 : 0);
    int bt_col_off = (lane & 16) ? 8 : 0;

    #pragma unroll
    for (int u = 0; u < 2; u++) {
        int s = tid + u * 256;
        int row = s >> 3, col = (s & 7) * 8;
        cp_async16(qb + (uint32_t)(row * SST + col) * 2,
                   Q + (size_t)(b * Sz + it * 64 + row) * ldqk + h * DHz + col);
    }
    CP_COMMIT();
    #pragma unroll
    for (int u = 0; u < 2; u++) {
        int s = tid + u * 256;
        int row = s >> 3, col = (s & 7) * 8;
        cp_async16(kb0 + (uint32_t)(row * SST + col) * 2,
                   Kb + (size_t)(b * Sz + row) * ldqk + h * DHz + col);
    }
    CP_COMMIT();

    float psum[2][2] = {};

    // ---------------- pass 1: S, exp, P -> smem ----------------
    for (int kt = 0; kt <= it; kt++) {
        CP_WAIT(0);
        __syncthreads();
        if (kt < it) {
            uint32_t nb = kb0 + (uint32_t)(((kt + 1) & 1) * 64 * SST * 2);
            #pragma unroll
            for (int u = 0; u < 2; u++) {
                int s = tid + u * 256;
                int row = s >> 3, col = (s & 7) * 8;
                cp_async16(nb + (uint32_t)(row * SST + col) * 2,
                           Kb + (size_t)(b * Sz + (kt + 1) * 64 + row) * ldqk
                               + h * DHz + col);
            }
            CP_COMMIT();
        }
        uint32_t kb = kb0 + (uint32_t)((kt & 1) * 64 * SST * 2);

        float accS[2][2][4] = {};
        #pragma unroll
        for (int ks = 0; ks < 4; ks++) {
            int kc = ks * 16;
            uint32_t af[2][4];
            #pragma unroll
            for (int im = 0; im < 2; im++) {
                int row = warp_m * 32 + im * 16 + a_row_off;
                ldm_x4(af[im], qb + (uint32_t)(row * SST + kc + a_col_off) * 2);
            }
            uint32_t bf[4];
            {
                int row = warp_n * 16 + b_row_off;
                ldm_x4(bf, kb + (uint32_t)(row * SST + kc + b_col_off) * 2);
            }
            #pragma unroll
            for (int im = 0; im < 2; im++) {
                mma_f16(accS[im][0], af[im], bf[0], bf[1]);
                mma_f16(accS[im][1], af[im], bf[2], bf[3]);
            }
        }

        int diag = (kt == it);
        #pragma unroll
        for (int im = 0; im < 2; im++) {
            int r0 = warp_m * 32 + im * 16 + lg;
            int g0 = it * 64 + r0, g1 = g0 + 8;
            #pragma unroll
            for (int nt = 0; nt < 2; nt++) {
                int gc = kt * 64 + warp_n * 16 + nt * 8 + 2 * lq;
                float p00 = __expf(accS[im][nt][0] * 0.125f);
                float p01 = __expf(accS[im][nt][1] * 0.125f);
                float p10 = __expf(accS[im][nt][2] * 0.125f);
                float p11 = __expf(accS[im][nt][3] * 0.125f);
                if (diag) {
                    if (gc     > g0) p00 = 0.f;
                    if (gc + 1 > g0) p01 = 0.f;
                    if (gc     > g1) p10 = 0.f;
                    if (gc + 1 > g1) p11 = 0.f;
                }
                psum[im][0] += p00 + p01;
                psum[im][1] += p10 + p11;
                *(__half2*)&Ps[r0 * PST + gc]       = __floats2half2_rn(p00, p01);
                *(__half2*)&Ps[(r0 + 8) * PST + gc] = __floats2half2_rn(p10, p11);
            }
        }
    }

    __syncthreads();

    // prefetch V[0] (rows = s 0..63, cols = d 0..63, from qkvh layout)
    #pragma unroll
    for (int u = 0; u < 2; u++) {
        int s = tid + u * 256;
        int row = s >> 3, col = (s & 7) * 8;
        cp_async16(kb0 + (uint32_t)(row * SST + col) * 2,
                   V + (size_t)(b * Sz + row) * ldqk + h * DHz + col);
    }
    CP_COMMIT();

    // row-sum reduce -> linv
    #pragma unroll
    for (int im = 0; im < 2; im++)
        #pragma unroll
        for (int rh = 0; rh < 2; rh++) {
            float v = psum[im][rh];
            v += __shfl_xor_sync(0xffffffff, v, 1);
            v += __shfl_xor_sync(0xffffffff, v, 2);
            if (lq == 0) {
                int row = warp_m * 32 + im * 16 + lg + rh * 8;
                red[warp_n * 64 + row] = v;
            }
        }
    __syncthreads();
    if (tid < 64) {
        float l = red[tid] + red[64 + tid] + red[128 + tid] + red[192 + tid];
        linv[tid] = 1.f / l;
    }
    __syncthreads();

    // ---------------- pass 2: O = P @ V ----------------
    float accO[2][2][4] = {};
    for (int kt = 0; kt <= it; kt++) {
        CP_WAIT(0);
        __syncthreads();
        if (kt < it) {
            uint32_t nb = kb0 + (uint32_t)(((kt + 1) & 1) * 64 * SST * 2);
            #pragma unroll
            for (int u = 0; u < 2; u++) {
                int s = tid + u * 256;
                int row = s >> 3, col = (s & 7) * 8;
                cp_async16(nb + (uint32_t)(row * SST + col) * 2,
                           V + (size_t)(b * Sz + (kt + 1) * 64 + row) * ldqk
                               + h * DHz + col);
            }
            CP_COMMIT();
        }
        uint32_t vb = kb0 + (uint32_t)((kt & 1) * 64 * SST * 2);

        #pragma unroll
        for (int ks = 0; ks < 4; ks++) {
            int kc = kt * 64 + ks * 16;
            uint32_t af[2][4];
            #pragma unroll
            for (int im = 0; im < 2; im++) {
                int row = warp_m * 32 + im * 16 + a_row_off;
                ldm_x4(af[im], pb + (uint32_t)(row * PST + kc + a_col_off) * 2);
            }
            uint32_t bf[4];
            {
                // V tile is [s][d]; trans load: row = k(s), col = n(d)
                int krow = ks * 16 + bt_row_off;
                int ncol = warp_n * 16 + bt_col_off;
                ldm_x4_trans(bf, vb + (uint32_t)(krow * SST + ncol) * 2);
            }
            #pragma unroll
            for (int im = 0; im < 2; im++) {
                mma_f16(accO[im][0], af[im], bf[0], bf[1]);
                mma_f16(accO[im][1], af[im], bf[2], bf[3]);
            }
        }
    }

    // ctx write (normalized)
    #pragma unroll
    for (int im = 0; im < 2; im++) {
        int r0 = warp_m * 32 + im * 16 + lg;
        float il0 = linv[r0], il1 = linv[r0 + 8];
        int gr = it * 64 + r0;
        #pragma unroll
        for (int nt = 0; nt < 2; nt++) {
            int d = warp_n * 16 + nt * 8 + 2 * lq;
            __half* p0 = ctxh + ((size_t)(b * Sz) + gr) * Dz + h * DHz + d;
            __half* p1 = p0 + (size_t)8 * Dz;
            *(__half2*)p0 = __floats2half2_rn(accO[im][nt][0] * il0,
                                              accO[im][nt][1] * il0);
            *(__half2*)p1 = __floats2half2_rn(accO[im][nt][2] * il1,
                                              accO[im][nt][3] * il1);
        }
    }

    // attn write
    for (int j = 0; j < 64; j++) {
        int grow = it * 64 + j;
        int limit = grow + 1;
        float il = linv[j];
        int col = tid * 4;
        float4 o;
        o.x = (col     < limit) ? __half2float(Ps[j * PST + col])     * il : 0.f;
        o.y = (col + 1 < limit) ? __half2float(Ps[j * PST + col + 1]) * il : 0.f;
        o.z = (col + 2 < limit) ? __half2float(Ps[j * PST + col + 2]) * il : 0.f;
        o.w = (col + 3 < limit) ? __half2float(Ps[j * PST + col + 3]) * il : 0.f;
        *(float4*)(attn + ((size_t)bh * Sz + grow) * Sz + col) = o;
    }
}

// ===================== residual + LayerNorm (fp32, optional half out) =======
__global__ __launch_bounds__(256) void add_ln_kernel(
    const float* __restrict__ x, const float* __restrict__ r,
    const float* __restrict__ g, const float* __restrict__ be,
    float* __restrict__ out, __half* __restrict__ outh)
{
    int row = blockIdx.x;
    const float* xr = x + (size_t)row * Dz;
    const float* rr = r + (size_t)row * Dz;
    float* orow = out + (size_t)row * Dz;
    int tid = threadIdx.x;

    float v[4];
    float lsum = 0.f, lsq = 0.f;
    #pragma unroll
    for (int u = 0; u < 4; u++) {
        int c = tid + u * 256;
        v[u] = xr[c] + rr[c];
        lsum += v[u];
        lsq  += v[u] * v[u];
    }

    __shared__ float s1[256], s2[256];
    s1[tid] = lsum; s2[tid] = lsq;
    __syncthreads();
    #pragma unroll
    for (int s = 128; s > 0; s >>= 1) {
        if (tid < s) { s1[tid] += s1[tid + s]; s2[tid] += s2[tid + s]; }
        __syncthreads();
    }
    float mean = s1[0] * (1.f / Dz);
    float var  = s2[0] * (1.f / Dz) - mean * mean;
    float inv  = rsqrtf(var + 1e-5f);

    #pragma unroll
    for (int u = 0; u < 4; u++) {
        int c = tid + u * 256;
        float o = (v[u] - mean) * inv * g[c] + be[c];
        orow[c] = o;
        if (outh) outh[(size_t)row * Dz + c] = __float2half_rn(o);
    }
}

// ===================== host launch ==========================================
extern "C" void kernel_launch(void* const* d_in, const int* in_sizes, int n_in,
                              void* d_out, int out_size)
{
    const float* x    = (const float*)d_in[0];
    const float* Wq   = (const float*)d_in[1];
    const float* bq   = (const float*)d_in[2];
    const float* Wk   = (const float*)d_in[3];
    const float* bk   = (const float*)d_in[4];
    const float* Wv   = (const float*)d_in[5];
    const float* bv   = (const float*)d_in[6];
    const float* Wo   = (const float*)d_in[7];
    const float* bo   = (const float*)d_in[8];
    const float* ln1g = (const float*)d_in[9];
    const float* ln1b = (const float*)d_in[10];
    const float* W1   = (const float*)d_in[11];
    const float* b1   = (const float*)d_in[12];
    const float* W2   = (const float*)d_in[13];
    const float* b2   = (const float*)d_in[14];
    const float* ln2g = (const float*)d_in[15];
    const float* ln2b = (const float*)d_in[16];

    float* out  = (float*)d_out;
    float* y    = out;
    float* attn = out + (size_t)BSz * Dz;

    float *t1, *h, *bqkv;
    __half *xh, *qkvh, *ctxh, *hh, *ffh;
    __half *wqkvh, *woh, *w1h, *w2h;
    cudaGetSymbolAddress((void**)&t1,   g_t1);
    cudaGetSymbolAddress((void**)&h,    g_h);
    cudaGetSymbolAddress((void**)&bqkv, g_bqkv);
    cudaGetSymbolAddress((void**)&xh,   g_xh);
    cudaGetSymbolAddress((void**)&qkvh, g_qkvh);
    cudaGetSymbolAddress((void**)&ctxh, g_ctxh);
    cudaGetSymbolAddress((void**)&hh,   g_hh);
    cudaGetSymbolAddress((void**)&ffh,  g_ffh);
    cudaGetSymbolAddress((void**)&wqkvh, g_wqkvh);
    cudaGetSymbolAddress((void**)&woh,  g_woh);
    cudaGetSymbolAddress((void**)&w1h,  g_w1h);
    cudaGetSymbolAddress((void**)&w2h,  g_w2h);

    cudaFuncSetAttribute(hgemm_kernel,
                         cudaFuncAttributeMaxDynamicSharedMemorySize, GEMM_SMEM);
    cudaFuncSetAttribute(attn_fused_kernel,
                         cudaFuncAttributeMaxDynamicSharedMemorySize, ATT_SMEM);

    const __half* qh = qkvh;
    const __half* kh = qkvh + Dz;
    const __half* vh = qkvh + 2 * Dz;

    dim3 tDD(Dz / 32, Dz / 32);
    dim3 gQKV(QKVN / GBN, BSz / GBM);   // 12 x 32 = 384 CTAs
    dim3 gDD(Dz / GBN, BSz / GBM);      // 4 x 32 = 128 CTAs
    dim3 gDF(FFz / GBN, BSz / GBM);     // 16 x 32 = 512 CTAs

    Ptr3 wsrc; wsrc.p[0] = Wq; wsrc.p[1] = Wk; wsrc.p[2] = Wv;

    cvt_half_kernel<<<(BSz * Dz) / 1024, 256>>>(x, xh);                       // 0
    transpose_qkv_kernel<<<dim3(Dz / 32, Dz / 32, 3), 256>>>(wsrc, wqkvh);    // 1
    bias_concat_kernel<<<QKVN / 256, 256>>>(bq, bk, bv, bqkv);                // 2
    hgemm_kernel<<<gQKV, 512, GEMM_SMEM>>>(xh, wqkvh, bqkv, nullptr, qkvh,
                                           BSz, QKVN, Dz, 0);                 // 3
    transpose_half_kernel<<<dim3(FFz / 32, Dz / 32), 256>>>(W1, w1h, Dz, FFz);// 4

    attn_fused_kernel<<<dim3(Sz / 64, BHz), 256, ATT_SMEM>>>(
        qh, kh, vh, QKVN, attn, ctxh);                                        // 5

    transpose_half_kernel<<<tDD, 256>>>(Wo, woh, Dz, Dz);                     // 6
    hgemm_kernel<<<gDD, 512, GEMM_SMEM>>>(ctxh, woh, bo, t1, nullptr,
                                          BSz, Dz, Dz, 0);                    // 7
    add_ln_kernel<<<BSz, 256>>>(x, t1, ln1g, ln1b, h, hh);                    // 8
    transpose_half_kernel<<<dim3(Dz / 32, FFz / 32), 256>>>(W2, w2h, FFz, Dz);// 9
    hgemm_kernel<<<gDF, 512, GEMM_SMEM>>>(hh, w1h, b1, nullptr, ffh,
                                          BSz, FFz, Dz, 1);                   // 10
    hgemm_kernel<<<gDD, 512, GEMM_SMEM>>>(ffh, w2h, b2, t1, nullptr,
                                          BSz, Dz, FFz, 0);                   // 11
    add_ln_kernel<<<BSz, 256>>>(h, t1, ln2g, ln2b, y, nullptr);               // 12
}

// round 14
// speedup vs baseline: 1.2587x; 1.0151x over previous
#include <cuda_runtime.h>
#include <cuda_fp16.h>
#include <math.h>
#include <stdint.h>

#define Bz 4
#define Sz 1024
#define Dz 1024
#define Hz 16
#define DHz 64
#define FFz 4096
#define BSz (Bz*Sz)      // 4096
#define BHz (Bz*Hz)      // 64
#define QKVN (3*Dz)      // 3072

// ===================== scratch ==============================================
__device__ float  g_t1 [BSz*Dz];      // attn_out, then ff2 (fp32 residual)
__device__ float  g_h  [BSz*Dz];      // h (fp32)
__device__ float  g_bqkv[QKVN];       // concat bias
__device__ __half g_xh  [BSz*Dz];
__device__ __half g_qkvh[(size_t)BSz*QKVN];   // fused q|k|v, row stride 3072
__device__ __half g_ctxh[BSz*Dz];
__device__ __half g_hh  [BSz*Dz];
__device__ __half g_ffh [BSz*FFz];
__device__ __half g_wqkvh[(size_t)QKVN*Dz];   // [3072][1024] = WqT|WkT|WvT
__device__ __half g_woh [Dz*Dz];
__device__ __half g_w1h [(size_t)Dz*FFz];
__device__ __half g_w2h [(size_t)Dz*FFz];

// ===================== helpers ==============================================
__device__ __forceinline__ uint32_t smem_u32(const void* p) {
    uint32_t a;
    asm("{ .reg .u64 t; cvta.to.shared.u64 t, %1; cvt.u32.u64 %0, t; }"
        : "=r"(a) : "l"(p));
    return a;
}
__device__ __forceinline__ void cp_async16(uint32_t dst, const void* src) {
    asm volatile("cp.async.cg.shared.global [%0], [%1], 16;"
                 :: "r"(dst), "l"(src));
}
#define CP_COMMIT() asm volatile("cp.async.commit_group;" ::: "memory")
#define CP_WAIT(n)  asm volatile("cp.async.wait_group %0;" :: "n"(n) : "memory")

__device__ __forceinline__ void ldm_x4(uint32_t* r, uint32_t addr) {
    asm volatile("ldmatrix.sync.aligned.m8n8.x4.shared.b16 {%0,%1,%2,%3}, [%4];"
                 : "=r"(r[0]), "=r"(r[1]), "=r"(r[2]), "=r"(r[3]) : "r"(addr));
}
__device__ __forceinline__ void ldm_x4_trans(uint32_t* r, uint32_t addr) {
    asm volatile("ldmatrix.sync.aligned.m8n8.x4.trans.shared.b16 {%0,%1,%2,%3}, [%4];"
                 : "=r"(r[0]), "=r"(r[1]), "=r"(r[2]), "=r"(r[3]) : "r"(addr));
}
__device__ __forceinline__ void mma_f16(float* c, const uint32_t* a,
                                        uint32_t b0, uint32_t b1) {
    asm volatile(
        "mma.sync.aligned.m16n8k16.row.col.f32.f16.f16.f32 "
        "{%0,%1,%2,%3}, {%4,%5,%6,%7}, {%8,%9}, {%0,%1,%2,%3};"
        : "+f"(c[0]), "+f"(c[1]), "+f"(c[2]), "+f"(c[3])
        : "r"(a[0]), "r"(a[1]), "r"(a[2]), "r"(a[3]), "r"(b0), "r"(b1));
}

// ===================== batched weight transpose (QKV) =======================
struct Ptr3 { const float* p[3]; };
__global__ __launch_bounds__(256) void transpose_qkv_kernel(
    Ptr3 srcs, __half* __restrict__ out)
{
    __shared__ float t[32][33];
    int z = blockIdx.z;
    const float* in = srcs.p[z];
    __half* o = out + (size_t)z * Dz * Dz;
    int c0 = blockIdx.x * 32, r0 = blockIdx.y * 32;
    int x = threadIdx.x & 31, y = threadIdx.x >> 5;
    #pragma unroll
    for (int u = 0; u < 4; u++)
        t[y + 8 * u][x] = in[(size_t)(r0 + y + 8 * u) * Dz + c0 + x];
    __syncthreads();
    #pragma unroll
    for (int u = 0; u < 4; u++)
        o[(size_t)(c0 + y + 8 * u) * Dz + r0 + x] = __float2half_rn(t[x][y + 8 * u]);
}

// ===================== generic weight transpose =============================
__global__ __launch_bounds__(256) void transpose_half_kernel(
    const float* __restrict__ in, __half* __restrict__ out, int R, int C)
{
    __shared__ float t[32][33];
    int c0 = blockIdx.x * 32, r0 = blockIdx.y * 32;
    int x = threadIdx.x & 31, y = threadIdx.x >> 5;
    #pragma unroll
    for (int u = 0; u < 4; u++)
        t[y + 8 * u][x] = in[(size_t)(r0 + y + 8 * u) * C + c0 + x];
    __syncthreads();
    #pragma unroll
    for (int u = 0; u < 4; u++)
        out[(size_t)(c0 + y + 8 * u) * R + r0 + x] = __float2half_rn(t[x][y + 8 * u]);
}

// ===================== bias concat ==========================================
__global__ __launch_bounds__(256) void bias_concat_kernel(
    const float* __restrict__ bq, const float* __restrict__ bk,
    const float* __restrict__ bv, float* __restrict__ o)
{
    int i = blockIdx.x * 256 + threadIdx.x;
    float v = (i < Dz) ? bq[i] : (i < 2 * Dz) ? bk[i - Dz] : bv[i - 2 * Dz];
    o[i] = v;
}

// ===================== cvt copy: out_h = half(in) ===========================
__global__ __launch_bounds__(256) void cvt_half_kernel(
    const float* __restrict__ in, __half* __restrict__ out)
{
    size_t i = ((size_t)blockIdx.x * 256 + threadIdx.x) * 4;
    float4 v = *(const float4*)(in + i);
    __half2* o = (__half2*)(out + i);
    o[0] = __floats2half2_rn(v.x, v.y);
    o[1] = __floats2half2_rn(v.z, v.w);
}

// ===================== FP16 mma GEMM: 128x256x64, 512 thr, 3-stage ==========
#define GBM 128
#define GBN 256
#define GBK 64
#define KST2 72
#define STG_A 18432
#define STG_BYTES 55296
#define NSTAGE 3
#define GEMM_SMEM (NSTAGE * STG_BYTES)   // 165888

__global__ __launch_bounds__(512) void hgemm_kernel(
    const __half* __restrict__ A, const __half* __restrict__ Bt,
    const float* __restrict__ bias, float* __restrict__ Cf,
    __half* __restrict__ Ch, int M, int N, int K, int relu)
{
    extern __shared__ __half hsm[];
    uint32_t sbase = smem_u32(hsm);
    int tid = threadIdx.x;
    int wid = tid >> 5, lane = tid & 31;
    int m0 = blockIdx.y * GBM, n0 = blockIdx.x * GBN;
    int warp_m = wid >> 3, warp_n = wid & 7;
    int lg = lane >> 2, lq = lane & 3;

    float acc[4][4][4] = {};

    int row0 = tid >> 3, col0 = (tid & 7) * 8;
    uint32_t offA = (uint32_t)(row0 * KST2 + col0) * 2;
    const __half* Ap = A  + (size_t)(m0 + row0) * K + col0;
    const __half* Bp = Bt + (size_t)(n0 + row0) * K + col0;
    const size_t K64 = (size_t)64 * K;

    const int nchunks = K / GBK;

    #pragma unroll
    for (int pc = 0; pc < 2; pc++) {
        uint32_t base = sbase + (uint32_t)pc * STG_BYTES;
        size_t koff = (size_t)pc * GBK;
        cp_async16(base + offA,                 Ap + koff);
        cp_async16(base + offA + 64*KST2*2,     Ap + koff + K64);
        uint32_t bb = base + STG_A + offA;
        cp_async16(bb,                  Bp + koff);
        cp_async16(bb + 64*KST2*2,      Bp + koff + K64);
        cp_async16(bb + 128*KST2*2,     Bp + koff + 2*K64);
        cp_async16(bb + 192*KST2*2,     Bp + koff + 3*K64);
        CP_COMMIT();
    }

    int a_row_off = (lane & 7) + ((lane & 8) ? 8 : 0);
    int a_col_off = (lane & 16) ? 8 : 0;
    int b_row_off = (lane & 7) + ((lane & 16) ? 8 : 0);
    int b_col_off = (lane & 8) ? 8 : 0;

    for (int c = 0; c < nchunks; c++) {
        CP_WAIT(1);
        __syncthreads();

        if (c + 2 < nchunks) {
            uint32_t base = sbase + (uint32_t)((c + 2) % NSTAGE) * STG_BYTES;
            size_t koff = (size_t)(c + 2) * GBK;
            cp_async16(base + offA,                 Ap + koff);
            cp_async16(base + offA + 64*KST2*2,     Ap + koff + K64);
            uint32_t bb = base + STG_A + offA;
            cp_async16(bb,                  Bp + koff);
            cp_async16(bb + 64*KST2*2,      Bp + koff + K64);
            cp_async16(bb + 128*KST2*2,     Bp + koff + 2*K64);
            cp_async16(bb + 192*KST2*2,     Bp + koff + 3*K64);
        }
        CP_COMMIT();

        uint32_t abase = sbase + (uint32_t)(c % NSTAGE) * STG_BYTES;
        uint32_t bbase = abase + STG_A;

        #pragma unroll
        for (int ks = 0; ks < 4; ks++) {
            int kc = ks * 16;
            uint32_t af[4][4];
            #pragma unroll
            for (int im = 0; im < 4; im++) {
                int row = warp_m * 64 + im * 16 + a_row_off;
                ldm_x4(af[im], abase + (uint32_t)(row * KST2 + kc + a_col_off) * 2);
            }
            uint32_t bf[2][4];
            #pragma unroll
            for (int pr = 0; pr < 2; pr++) {
                int row = warp_n * 32 + pr * 16 + b_row_off;
                ldm_x4(bf[pr], bbase + (uint32_t)(row * KST2 + kc + b_col_off) * 2);
            }
            #pragma unroll
            for (int im = 0; im < 4; im++)
                #pragma unroll
                for (int pr = 0; pr < 2; pr++) {
                    mma_f16(acc[im][pr * 2 + 0], af[im], bf[pr][0], bf[pr][1]);
                    mma_f16(acc[im][pr * 2 + 1], af[im], bf[pr][2], bf[pr][3]);
                }
        }
    }

    #pragma unroll
    for (int im = 0; im < 4; im++) {
        int r0 = m0 + warp_m * 64 + im * 16 + lg;
        #pragma unroll
        for (int nt = 0; nt < 4; nt++) {
            int cc = n0 + warp_n * 32 + nt * 8 + 2 * lq;
            float b0 = bias[cc], b1 = bias[cc + 1];
            float v00 = acc[im][nt][0] + b0, v01 = acc[im][nt][1] + b1;
            float v10 = acc[im][nt][2] + b0, v11 = acc[im][nt][3] + b1;
            if (relu) {
                v00 = fmaxf(v00, 0.f); v01 = fmaxf(v01, 0.f);
                v10 = fmaxf(v10, 0.f); v11 = fmaxf(v11, 0.f);
            }
            if (Cf) {
                float2 a2; a2.x = v00; a2.y = v01;
                float2 b2; b2.x = v10; b2.y = v11;
                *(float2*)(Cf + (size_t)r0 * N + cc) = a2;
                *(float2*)(Cf + (size_t)(r0 + 8) * N + cc) = b2;
            }
            if (Ch) {
                *(__half2*)(Ch + (size_t)r0 * N + cc) = __floats2half2_rn(v00, v01);
                *(__half2*)(Ch + (size_t)(r0 + 8) * N + cc) = __floats2half2_rn(v10, v11);
            }
        }
    }
}

// ===================== fused attention ======================================
#define SST 72           // Q/K/V tile row stride (halfs)
#define PST 1032         // P row stride in halfs
#define ATT_SMEM 161024

__global__ __launch_bounds__(256) void attn_fused_kernel(
    const __half* __restrict__ Q, const __half* __restrict__ Kb,
    const __half* __restrict__ V, int ldqk,
    float* __restrict__ attn, __half* __restrict__ ctxh)
{
    extern __shared__ char asmem[];
    __half* Qs = (__half*)asmem;
    __half* Ks = Qs + 64 * SST;
    __half* Ps = Ks + 2 * 64 * SST;
    float* red  = (float*)(Ps + 64 * PST);
    float* linv = red + 256;
    uint32_t qb  = smem_u32(Qs);
    uint32_t kb0 = smem_u32(Ks);
    uint32_t pb  = smem_u32(Ps);

    int it = 15 - (int)blockIdx.x;
    int bh = blockIdx.y;
    int b = bh / Hz, h = bh % Hz;
    int tid = threadIdx.x, wid = tid >> 5, lane = tid & 31;
    int lg = lane >> 2, lq = lane & 3;
    int warp_m = wid >> 2, warp_n = wid & 3;
    int a_row_off = (lane & 7) + ((lane & 8) ? 8 : 0);
    int a_col_off = (lane & 16) ? 8 : 0;
    int b_row_off = (lane & 7) + ((lane & 16) ? 8 : 0);
    int b_col_off = (lane & 8) ? 8 : 0;
    int bt_row_off = (lane & 7) + ((lane & 8) ? 8 : 0);
    int bt_col_off = (lane & 16) ? 8 : 0;

    #pragma unroll
    for (int u = 0; u < 2; u++) {
        int s = tid + u * 256;
        int row = s >> 3, col = (s & 7) * 8;
        cp_async16(qb + (uint32_t)(row * SST + col) * 2,
                   Q + (size_t)(b * Sz + it * 64 + row) * ldqk + h * DHz + col);
    }
    CP_COMMIT();
    #pragma unroll
    for (int u = 0; u < 2; u++) {
        int s = tid + u * 256;
        int row = s >> 3, col = (s & 7) * 8;
        cp_async16(kb0 + (uint32_t)(row * SST + col) * 2,
                   Kb + (size_t)(b * Sz + row) * ldqk + h * DHz + col);
    }
    CP_COMMIT();

    float psum[2][2] = {};

    // ---------------- pass 1: S, exp, P -> smem ----------------
    for (int kt = 0; kt <= it; kt++) {
        CP_WAIT(0);
        __syncthreads();
        if (kt < it) {
            uint32_t nb = kb0 + (uint32_t)(((kt + 1) & 1) * 64 * SST * 2);
            #pragma unroll
            for (int u = 0; u < 2; u++) {
                int s = tid + u * 256;
                int row = s >> 3, col = (s & 7) * 8;
                cp_async16(nb + (uint32_t)(row * SST + col) * 2,
                           Kb + (size_t)(b * Sz + (kt + 1) * 64 + row) * ldqk
                               + h * DHz + col);
            }
            CP_COMMIT();
        }
        uint32_t kb = kb0 + (uint32_t)((kt & 1) * 64 * SST * 2);

        float accS[2][2][4] = {};
        #pragma unroll
        for (int ks = 0; ks < 4; ks++) {
            int kc = ks * 16;
            uint32_t af[2][4];
            #pragma unroll
            for (int im = 0; im < 2; im++) {
                int row = warp_m * 32 + im * 16 + a_row_off;
                ldm_x4(af[im], qb + (uint32_t)(row * SST + kc + a_col_off) * 2);
            }
            uint32_t bf[4];
            {
                int row = warp_n * 16 + b_row_off;
                ldm_x4(bf, kb + (uint32_t)(row * SST + kc + b_col_off) * 2);
            }
            #pragma unroll
            for (int im = 0; im < 2; im++) {
                mma_f16(accS[im][0], af[im], bf[0], bf[1]);
                mma_f16(accS[im][1], af[im], bf[2], bf[3]);
            }
        }

        int diag = (kt == it);
        #pragma unroll
        for (int im = 0; im < 2; im++) {
            int r0 = warp_m * 32 + im * 16 + lg;
            int g0 = it * 64 + r0, g1 = g0 + 8;
            #pragma unroll
            for (int nt = 0; nt < 2; nt++) {
                int gc = kt * 64 + warp_n * 16 + nt * 8 + 2 * lq;
                float p00 = __expf(accS[im][nt][0] * 0.125f);
                float p01 = __expf(accS[im][nt][1] * 0.125f);
                float p10 = __expf(accS[im][nt][2] * 0.125f);
                float p11 = __expf(accS[im][nt][3] * 0.125f);
                if (diag) {
                    if (gc     > g0) p00 = 0.f;
                    if (gc + 1 > g0) p01 = 0.f;
                    if (gc     > g1) p10 = 0.f;
                    if (gc + 1 > g1) p11 = 0.f;
                }
                psum[im][0] += p00 + p01;
                psum[im][1] += p10 + p11;
                *(__half2*)&Ps[r0 * PST + gc]       = __floats2half2_rn(p00, p01);
                *(__half2*)&Ps[(r0 + 8) * PST + gc] = __floats2half2_rn(p10, p11);
            }
        }
    }

    __syncthreads();

    // prefetch V[0]
    #pragma unroll
    for (int u = 0; u < 2; u++) {
        int s = tid + u * 256;
        int row = s >> 3, col = (s & 7) * 8;
        cp_async16(kb0 + (uint32_t)(row * SST + col) * 2,
                   V + (size_t)(b * Sz + row) * ldqk + h * DHz + col);
    }
    CP_COMMIT();

    // row-sum reduce -> linv
    #pragma unroll
    for (int im = 0; im < 2; im++)
        #pragma unroll
        for (int rh = 0; rh < 2; rh++) {
            float v = psum[im][rh];
            v += __shfl_xor_sync(0xffffffff, v, 1);
            v += __shfl_xor_sync(0xffffffff, v, 2);
            if (lq == 0) {
                int row = warp_m * 32 + im * 16 + lg + rh * 8;
                red[warp_n * 64 + row] = v;
            }
        }
    __syncthreads();
    if (tid < 64) {
        float l = red[tid] + red[64 + tid] + red[128 + tid] + red[192 + tid];
        linv[tid] = 1.f / l;
    }
    __syncthreads();

    // ---------------- pass 2: O = P @ V ----------------
    float accO[2][2][4] = {};
    for (int kt = 0; kt <= it; kt++) {
        CP_WAIT(0);
        __syncthreads();
        if (kt < it) {
            uint32_t nb = kb0 + (uint32_t)(((kt + 1) & 1) * 64 * SST * 2);
            #pragma unroll
            for (int u = 0; u < 2; u++) {
                int s = tid + u * 256;
                int row = s >> 3, col = (s & 7) * 8;
                cp_async16(nb + (uint32_t)(row * SST + col) * 2,
                           V + (size_t)(b * Sz + (kt + 1) * 64 + row) * ldqk
                               + h * DHz + col);
            }
            CP_COMMIT();
        }
        uint32_t vb = kb0 + (uint32_t)((kt & 1) * 64 * SST * 2);

        #pragma unroll
        for (int ks = 0; ks < 4; ks++) {
            int kc = kt * 64 + ks * 16;
            uint32_t af[2][4];
            #pragma unroll
            for (int im = 0; im < 2; im++) {
                int row = warp_m * 32 + im * 16 + a_row_off;
                ldm_x4(af[im], pb + (uint32_t)(row * PST + kc + a_col_off) * 2);
            }
            uint32_t bf[4];
            {
                int krow = ks * 16 + bt_row_off;
                int ncol = warp_n * 16 + bt_col_off;
                ldm_x4_trans(bf, vb + (uint32_t)(krow * SST + ncol) * 2);
            }
            #pragma unroll
            for (int im = 0; im < 2; im++) {
                mma_f16(accO[im][0], af[im], bf[0], bf[1]);
                mma_f16(accO[im][1], af[im], bf[2], bf[3]);
            }
        }
    }

    // ctx write (normalized)
    #pragma unroll
    for (int im = 0; im < 2; im++) {
        int r0 = warp_m * 32 + im * 16 + lg;
        float il0 = linv[r0], il1 = linv[r0 + 8];
        int gr = it * 64 + r0;
        #pragma unroll
        for (int nt = 0; nt < 2; nt++) {
            int d = warp_n * 16 + nt * 8 + 2 * lq;
            __half* p0 = ctxh + ((size_t)(b * Sz) + gr) * Dz + h * DHz + d;
            __half* p1 = p0 + (size_t)8 * Dz;
            *(__half2*)p0 = __floats2half2_rn(accO[im][nt][0] * il0,
                                              accO[im][nt][1] * il0);
            *(__half2*)p1 = __floats2half2_rn(accO[im][nt][2] * il1,
                                              accO[im][nt][3] * il1);
        }
    }

    // attn write
    for (int j = 0; j < 64; j++) {
        int grow = it * 64 + j;
        int limit = grow + 1;
        float il = linv[j];
        int col = tid * 4;
        float4 o;
        o.x = (col     < limit) ? __half2float(Ps[j * PST + col])     * il : 0.f;
        o.y = (col + 1 < limit) ? __half2float(Ps[j * PST + col + 1]) * il : 0.f;
        o.z = (col + 2 < limit) ? __half2float(Ps[j * PST + col + 2]) * il : 0.f;
        o.w = (col + 3 < limit) ? __half2float(Ps[j * PST + col + 3]) * il : 0.f;
        *(float4*)(attn + ((size_t)bh * Sz + grow) * Sz + col) = o;
    }
}

// ===================== residual + LayerNorm (fp32, optional half out) =======
__global__ __launch_bounds__(256) void add_ln_kernel(
    const float* __restrict__ x, const float* __restrict__ r,
    const float* __restrict__ g, const float* __restrict__ be,
    float* __restrict__ out, __half* __restrict__ outh)
{
    int row = blockIdx.x;
    const float* xr = x + (size_t)row * Dz;
    const float* rr = r + (size_t)row * Dz;
    float* orow = out + (size_t)row * Dz;
    int tid = threadIdx.x;

    float v[4];
    float lsum = 0.f, lsq = 0.f;
    #pragma unroll
    for (int u = 0; u < 4; u++) {
        int c = tid + u * 256;
        v[u] = xr[c] + rr[c];
        lsum += v[u];
        lsq  += v[u] * v[u];
    }

    __shared__ float s1[256], s2[256];
    s1[tid] = lsum; s2[tid] = lsq;
    __syncthreads();
    #pragma unroll
    for (int s = 128; s > 0; s >>= 1) {
        if (tid < s) { s1[tid] += s1[tid + s]; s2[tid] += s2[tid + s]; }
        __syncthreads();
    }
    float mean = s1[0] * (1.f / Dz);
    float var  = s2[0] * (1.f / Dz) - mean * mean;
    float inv  = rsqrtf(var + 1e-5f);

    #pragma unroll
    for (int u = 0; u < 4; u++) {
        int c = tid + u * 256;
        float o = (v[u] - mean) * inv * g[c] + be[c];
        orow[c] = o;
        if (outh) outh[(size_t)row * Dz + c] = __float2half_rn(o);
    }
}

// ===================== host launch ==========================================
extern "C" void kernel_launch(void* const* d_in, const int* in_sizes, int n_in,
                              void* d_out, int out_size)
{
    const float* x    = (const float*)d_in[0];
    const float* Wq   = (const float*)d_in[1];
    const float* bq   = (const float*)d_in[2];
    const float* Wk   = (const float*)d_in[3];
    const float* bk   = (const float*)d_in[4];
    const float* Wv   = (const float*)d_in[5];
    const float* bv   = (const float*)d_in[6];
    const float* Wo   = (const float*)d_in[7];
    const float* bo   = (const float*)d_in[8];
    const float* ln1g = (const float*)d_in[9];
    const float* ln1b = (const float*)d_in[10];
    const float* W1   = (const float*)d_in[11];
    const float* b1   = (const float*)d_in[12];
    const float* W2   = (const float*)d_in[13];
    const float* b2   = (const float*)d_in[14];
    const float* ln2g = (const float*)d_in[15];
    const float* ln2b = (const float*)d_in[16];

    float* out  = (float*)d_out;
    float* y    = out;
    float* attn = out + (size_t)BSz * Dz;

    float *t1, *h, *bqkv;
    __half *xh, *qkvh, *ctxh, *hh, *ffh;
    __half *wqkvh, *woh, *w1h, *w2h;
    cudaGetSymbolAddress((void**)&t1,   g_t1);
    cudaGetSymbolAddress((void**)&h,    g_h);
    cudaGetSymbolAddress((void**)&bqkv, g_bqkv);
    cudaGetSymbolAddress((void**)&xh,   g_xh);
    cudaGetSymbolAddress((void**)&qkvh, g_qkvh);
    cudaGetSymbolAddress((void**)&ctxh, g_ctxh);
    cudaGetSymbolAddress((void**)&hh,   g_hh);
    cudaGetSymbolAddress((void**)&ffh,  g_ffh);
    cudaGetSymbolAddress((void**)&wqkvh, g_wqkvh);
    cudaGetSymbolAddress((void**)&woh,  g_woh);
    cudaGetSymbolAddress((void**)&w1h,  g_w1h);
    cudaGetSymbolAddress((void**)&w2h,  g_w2h);

    cudaFuncSetAttribute(hgemm_kernel,
                         cudaFuncAttributeMaxDynamicSharedMemorySize, GEMM_SMEM);
    cudaFuncSetAttribute(attn_fused_kernel,
                         cudaFuncAttributeMaxDynamicSharedMemorySize, ATT_SMEM);

    // side stream + events: created once (correctness run happens before
    // graph capture, so creation never occurs inside capture)
    static cudaStream_t s2 = nullptr;
    static cudaEvent_t evFork = nullptr, evJoin = nullptr;
    if (s2 == nullptr) {
        cudaStreamCreateWithFlags(&s2, cudaStreamNonBlocking);
        cudaEventCreateWithFlags(&evFork, cudaEventDisableTiming);
        cudaEventCreateWithFlags(&evJoin, cudaEventDisableTiming);
    }

    const __half* qh = qkvh;
    const __half* kh = qkvh + Dz;
    const __half* vh = qkvh + 2 * Dz;

    dim3 tDD(Dz / 32, Dz / 32);
    dim3 gQKV(QKVN / GBN, BSz / GBM);   // 12 x 32 = 384 CTAs
    dim3 gDD(Dz / GBN, BSz / GBM);      // 4 x 32 = 128 CTAs
    dim3 gDF(FFz / GBN, BSz / GBM);     // 16 x 32 = 512 CTAs

    Ptr3 wsrc; wsrc.p[0] = Wq; wsrc.p[1] = Wk; wsrc.p[2] = Wv;

    // fork side stream: Wo/W1/W2 transposes run concurrently with the main
    // chain (their consumers are launches far down the timeline)
    cudaEventRecord(evFork, 0);
    cudaStreamWaitEvent(s2, evFork, 0);
    transpose_half_kernel<<<dim3(FFz / 32, Dz / 32), 256, 0, s2>>>(W1, w1h, Dz, FFz);
    transpose_half_kernel<<<tDD, 256, 0, s2>>>(Wo, woh, Dz, Dz);
    transpose_half_kernel<<<dim3(Dz / 32, FFz / 32), 256, 0, s2>>>(W2, w2h, FFz, Dz);
    cudaEventRecord(evJoin, s2);

    // main chain
    cvt_half_kernel<<<(BSz * Dz) / 1024, 256>>>(x, xh);
    transpose_qkv_kernel<<<dim3(Dz / 32, Dz / 32, 3), 256>>>(wsrc, wqkvh);
    bias_concat_kernel<<<QKVN / 256, 256>>>(bq, bk, bv, bqkv);
    hgemm_kernel<<<gQKV, 512, GEMM_SMEM>>>(xh, wqkvh, bqkv, nullptr, qkvh,
                                           BSz, QKVN, Dz, 0);

    attn_fused_kernel<<<dim3(Sz / 64, BHz), 256, ATT_SMEM>>>(
        qh, kh, vh, QKVN, attn, ctxh);

    cudaStreamWaitEvent(0, evJoin, 0);   // Wo/W1/W2 halves ready
    hgemm_kernel<<<gDD, 512, GEMM_SMEM>>>(ctxh, woh, bo, t1, nullptr,
                                          BSz, Dz, Dz, 0);
    add_ln_kernel<<<BSz, 256>>>(x, t1, ln1g, ln1b, h, hh);
    hgemm_kernel<<<gDF, 512, GEMM_SMEM>>>(hh, w1h, b1, nullptr, ffh,
                                          BSz, FFz, Dz, 1);
    hgemm_kernel<<<gDD, 512, GEMM_SMEM>>>(ffh, w2h, b2, t1, nullptr,
                                          BSz, Dz, FFz, 0);
    add_ln_kernel<<<BSz, 256>>>(h, t1, ln2g, ln2b, y, nullptr);
}

// round 15
// speedup vs baseline: 1.2988x; 1.0319x over previous
#include <cuda_runtime.h>
#include <cuda_fp16.h>
#include <math.h>
#include <stdint.h>

#define Bz 4
#define Sz 1024
#define Dz 1024
#define Hz 16
#define DHz 64
#define FFz 4096
#define BSz (Bz*Sz)      // 4096
#define BHz (Bz*Hz)      // 64
#define QKVN (3*Dz)      // 3072

// ===================== scratch ==============================================
__device__ float  g_t1 [BSz*Dz];      // attn_out, then ff2 (fp32 residual)
__device__ float  g_h  [BSz*Dz];      // h (fp32)
__device__ float  g_bqkv[QKVN];       // concat bias
__device__ __half g_xh  [BSz*Dz];
__device__ __half g_qkvh[(size_t)BSz*QKVN];   // fused q|k|v, row stride 3072
__device__ __half g_ctxh[BSz*Dz];
__device__ __half g_hh  [BSz*Dz];
__device__ __half g_ffh [BSz*FFz];
__device__ __half g_wqkvh[(size_t)QKVN*Dz];   // [3072][1024] = WqT|WkT|WvT
__device__ __half g_woh [Dz*Dz];
__device__ __half g_w1h [(size_t)Dz*FFz];
__device__ __half g_w2h [(size_t)Dz*FFz];

// ===================== helpers ==============================================
__device__ __forceinline__ uint32_t smem_u32(const void* p) {
    uint32_t a;
    asm("{ .reg .u64 t; cvta.to.shared.u64 t, %1; cvt.u32.u64 %0, t; }"
        : "=r"(a) : "l"(p));
    return a;
}
__device__ __forceinline__ void cp_async16(uint32_t dst, const void* src) {
    asm volatile("cp.async.cg.shared.global [%0], [%1], 16;"
                 :: "r"(dst), "l"(src));
}
#define CP_COMMIT() asm volatile("cp.async.commit_group;" ::: "memory")
#define CP_WAIT(n)  asm volatile("cp.async.wait_group %0;" :: "n"(n) : "memory")

__device__ __forceinline__ void ldm_x4(uint32_t* r, uint32_t addr) {
    asm volatile("ldmatrix.sync.aligned.m8n8.x4.shared.b16 {%0,%1,%2,%3}, [%4];"
                 : "=r"(r[0]), "=r"(r[1]), "=r"(r[2]), "=r"(r[3]) : "r"(addr));
}
__device__ __forceinline__ void ldm_x4_trans(uint32_t* r, uint32_t addr) {
    asm volatile("ldmatrix.sync.aligned.m8n8.x4.trans.shared.b16 {%0,%1,%2,%3}, [%4];"
                 : "=r"(r[0]), "=r"(r[1]), "=r"(r[2]), "=r"(r[3]) : "r"(addr));
}
__device__ __forceinline__ void mma_f16(float* c, const uint32_t* a,
                                        uint32_t b0, uint32_t b1) {
    asm volatile(
        "mma.sync.aligned.m16n8k16.row.col.f32.f16.f16.f32 "
        "{%0,%1,%2,%3}, {%4,%5,%6,%7}, {%8,%9}, {%0,%1,%2,%3};"
        : "+f"(c[0]), "+f"(c[1]), "+f"(c[2]), "+f"(c[3])
        : "r"(a[0]), "r"(a[1]), "r"(a[2]), "r"(a[3]), "r"(b0), "r"(b1));
}

// ===================== batched weight transpose (QKV) =======================
struct Ptr3 { const float* p[3]; };
__global__ __launch_bounds__(256) void transpose_qkv_kernel(
    Ptr3 srcs, __half* __restrict__ out)
{
    __shared__ float t[32][33];
    int z = blockIdx.z;
    const float* in = srcs.p[z];
    __half* o = out + (size_t)z * Dz * Dz;
    int c0 = blockIdx.x * 32, r0 = blockIdx.y * 32;
    int x = threadIdx.x & 31, y = threadIdx.x >> 5;
    #pragma unroll
    for (int u = 0; u < 4; u++)
        t[y + 8 * u][x] = in[(size_t)(r0 + y + 8 * u) * Dz + c0 + x];
    __syncthreads();
    #pragma unroll
    for (int u = 0; u < 4; u++)
        o[(size_t)(c0 + y + 8 * u) * Dz + r0 + x] = __float2half_rn(t[x][y + 8 * u]);
}

// ===================== generic weight transpose =============================
__global__ __launch_bounds__(256) void transpose_half_kernel(
    const float* __restrict__ in, __half* __restrict__ out, int R, int C)
{
    __shared__ float t[32][33];
    int c0 = blockIdx.x * 32, r0 = blockIdx.y * 32;
    int x = threadIdx.x & 31, y = threadIdx.x >> 5;
    #pragma unroll
    for (int u = 0; u < 4; u++)
        t[y + 8 * u][x] = in[(size_t)(r0 + y + 8 * u) * C + c0 + x];
    __syncthreads();
    #pragma unroll
    for (int u = 0; u < 4; u++)
        out[(size_t)(c0 + y + 8 * u) * R + r0 + x] = __float2half_rn(t[x][y + 8 * u]);
}

// ===================== bias concat ==========================================
__global__ __launch_bounds__(256) void bias_concat_kernel(
    const float* __restrict__ bq, const float* __restrict__ bk,
    const float* __restrict__ bv, float* __restrict__ o)
{
    int i = blockIdx.x * 256 + threadIdx.x;
    float v = (i < Dz) ? bq[i] : (i < 2 * Dz) ? bk[i - Dz] : bv[i - 2 * Dz];
    o[i] = v;
}

// ===================== cvt copy: out_h = half(in) ===========================
__global__ __launch_bounds__(256) void cvt_half_kernel(
    const float* __restrict__ in, __half* __restrict__ out)
{
    size_t i = ((size_t)blockIdx.x * 256 + threadIdx.x) * 4;
    float4 v = *(const float4*)(in + i);
    __half2* o = (__half2*)(out + i);
    o[0] = __floats2half2_rn(v.x, v.y);
    o[1] = __floats2half2_rn(v.z, v.w);
}

// ===================== FP16 mma GEMM: 128x256x64, 512 thr, 3-stage ==========
#define GBM 128
#define GBN 256
#define GBK 64
#define KST2 72
#define STG_A 18432
#define STG_BYTES 55296
#define NSTAGE 3
#define GEMM_SMEM (NSTAGE * STG_BYTES)   // 165888

__global__ __launch_bounds__(512) void hgemm_kernel(
    const __half* __restrict__ A, const __half* __restrict__ Bt,
    const float* __restrict__ bias, float* __restrict__ Cf,
    __half* __restrict__ Ch, int M, int N, int K, int relu)
{
    extern __shared__ __half hsm[];
    uint32_t sbase = smem_u32(hsm);
    int tid = threadIdx.x;
    int wid = tid >> 5, lane = tid & 31;
    int m0 = blockIdx.y * GBM, n0 = blockIdx.x * GBN;
    int warp_m = wid >> 3, warp_n = wid & 7;
    int lg = lane >> 2, lq = lane & 3;

    float acc[4][4][4] = {};

    int row0 = tid >> 3, col0 = (tid & 7) * 8;
    uint32_t offA = (uint32_t)(row0 * KST2 + col0) * 2;
    const __half* Ap = A  + (size_t)(m0 + row0) * K + col0;
    const __half* Bp = Bt + (size_t)(n0 + row0) * K + col0;
    const size_t K64 = (size_t)64 * K;

    const int nchunks = K / GBK;

    #pragma unroll
    for (int pc = 0; pc < 2; pc++) {
        uint32_t base = sbase + (uint32_t)pc * STG_BYTES;
        size_t koff = (size_t)pc * GBK;
        cp_async16(base + offA,                 Ap + koff);
        cp_async16(base + offA + 64*KST2*2,     Ap + koff + K64);
        uint32_t bb = base + STG_A + offA;
        cp_async16(bb,                  Bp + koff);
        cp_async16(bb + 64*KST2*2,      Bp + koff + K64);
        cp_async16(bb + 128*KST2*2,     Bp + koff + 2*K64);
        cp_async16(bb + 192*KST2*2,     Bp + koff + 3*K64);
        CP_COMMIT();
    }

    int a_row_off = (lane & 7) + ((lane & 8) ? 8 : 0);
    int a_col_off = (lane & 16) ? 8 : 0;
    int b_row_off = (lane & 7) + ((lane & 16) ? 8 : 0);
    int b_col_off = (lane & 8) ? 8 : 0;

    for (int c = 0; c < nchunks; c++) {
        CP_WAIT(1);
        __syncthreads();

        if (c + 2 < nchunks) {
            uint32_t base = sbase + (uint32_t)((c + 2) % NSTAGE) * STG_BYTES;
            size_t koff = (size_t)(c + 2) * GBK;
            cp_async16(base + offA,                 Ap + koff);
            cp_async16(base + offA + 64*KST2*2,     Ap + koff + K64);
            uint32_t bb = base + STG_A + offA;
            cp_async16(bb,                  Bp + koff);
            cp_async16(bb + 64*KST2*2,      Bp + koff + K64);
            cp_async16(bb + 128*KST2*2,     Bp + koff + 2*K64);
            cp_async16(bb + 192*KST2*2,     Bp + koff + 3*K64);
        }
        CP_COMMIT();

        uint32_t abase = sbase + (uint32_t)(c % NSTAGE) * STG_BYTES;
        uint32_t bbase = abase + STG_A;

        #pragma unroll
        for (int ks = 0; ks < 4; ks++) {
            int kc = ks * 16;
            uint32_t af[4][4];
            #pragma unroll
            for (int im = 0; im < 4; im++) {
                int row = warp_m * 64 + im * 16 + a_row_off;
                ldm_x4(af[im], abase + (uint32_t)(row * KST2 + kc + a_col_off) * 2);
            }
            uint32_t bf[2][4];
            #pragma unroll
            for (int pr = 0; pr < 2; pr++) {
                int row = warp_n * 32 + pr * 16 + b_row_off;
                ldm_x4(bf[pr], bbase + (uint32_t)(row * KST2 + kc + b_col_off) * 2);
            }
            #pragma unroll
            for (int im = 0; im < 4; im++)
                #pragma unroll
                for (int pr = 0; pr < 2; pr++) {
                    mma_f16(acc[im][pr * 2 + 0], af[im], bf[pr][0], bf[pr][1]);
                    mma_f16(acc[im][pr * 2 + 1], af[im], bf[pr][2], bf[pr][3]);
                }
        }
    }

    #pragma unroll
    for (int im = 0; im < 4; im++) {
        int r0 = m0 + warp_m * 64 + im * 16 + lg;
        #pragma unroll
        for (int nt = 0; nt < 4; nt++) {
            int cc = n0 + warp_n * 32 + nt * 8 + 2 * lq;
            float b0 = bias[cc], b1 = bias[cc + 1];
            float v00 = acc[im][nt][0] + b0, v01 = acc[im][nt][1] + b1;
            float v10 = acc[im][nt][2] + b0, v11 = acc[im][nt][3] + b1;
            if (relu) {
                v00 = fmaxf(v00, 0.f); v01 = fmaxf(v01, 0.f);
                v10 = fmaxf(v10, 0.f); v11 = fmaxf(v11, 0.f);
            }
            if (Cf) {
                float2 a2; a2.x = v00; a2.y = v01;
                float2 b2; b2.x = v10; b2.y = v11;
                *(float2*)(Cf + (size_t)r0 * N + cc) = a2;
                *(float2*)(Cf + (size_t)(r0 + 8) * N + cc) = b2;
            }
            if (Ch) {
                *(__half2*)(Ch + (size_t)r0 * N + cc) = __floats2half2_rn(v00, v01);
                *(__half2*)(Ch + (size_t)(r0 + 8) * N + cc) = __floats2half2_rn(v10, v11);
            }
        }
    }
}

// ===================== fused attention (paired kt tiles) ====================
// Pass 1 processes TWO 64-col K tiles per barrier: warps 2m x 4n over
// 64x128 (warp tile 32x32, ratio 2.0). 4 K/V smem buffers, prefetch one
// pair ahead. Pass 2 keeps n=DH=64 layout but shares the paired barriers.
#define SST 72           // Q/K/V tile row stride (halfs)
#define PST 1032         // P row stride in halfs
#define KBUF (64 * SST)  // halfs per K/V buffer
#define ATT_SMEM 179456

__global__ __launch_bounds__(256) void attn_fused_kernel(
    const __half* __restrict__ Q, const __half* __restrict__ Kb,
    const __half* __restrict__ V, int ldqk,
    float* __restrict__ attn, __half* __restrict__ ctxh)
{
    extern __shared__ char asmem[];
    __half* Qs = (__half*)asmem;              // 64*SST
    __half* Ks = Qs + 64 * SST;               // 4 buffers of 64*SST
    __half* Ps = Ks + 4 * KBUF;               // 64*PST
    float* red  = (float*)(Ps + 64 * PST);    // [4][64]
    float* linv = red + 256;                  // [64]
    uint32_t qb  = smem_u32(Qs);
    uint32_t kb0 = smem_u32(Ks);
    uint32_t pb  = smem_u32(Ps);

    int it = 15 - (int)blockIdx.x;            // longest blocks first
    int bh = blockIdx.y;
    int b = bh / Hz, h = bh % Hz;
    int tid = threadIdx.x, wid = tid >> 5, lane = tid & 31;
    int lg = lane >> 2, lq = lane & 3;
    int warp_m = wid >> 2, warp_n = wid & 3;
    int a_row_off = (lane & 7) + ((lane & 8) ? 8 : 0);
    int a_col_off = (lane & 16) ? 8 : 0;
    int b_row_off = (lane & 7) + ((lane & 16) ? 8 : 0);
    int b_col_off = (lane & 8) ? 8 : 0;
    int bt_row_off = (lane & 7) + ((lane & 8) ? 8 : 0);
    int bt_col_off = (lane & 16) ? 8 : 0;

    // load Q
    #pragma unroll
    for (int u = 0; u < 2; u++) {
        int s = tid + u * 256;
        int row = s >> 3, col = (s & 7) * 8;
        cp_async16(qb + (uint32_t)(row * SST + col) * 2,
                   Q + (size_t)(b * Sz + it * 64 + row) * ldqk + h * DHz + col);
    }
    CP_COMMIT();
    // load K pair 0 (tiles 0, 1 if present) into buffers 0,1
    #pragma unroll
    for (int u = 0; u < 2; u++) {
        int s = tid + u * 256;
        int row = s >> 3, col = (s & 7) * 8;
        cp_async16(kb0 + (uint32_t)(row * SST + col) * 2,
                   Kb + (size_t)(b * Sz + row) * ldqk + h * DHz + col);
    }
    if (it >= 1) {
        #pragma unroll
        for (int u = 0; u < 2; u++) {
            int s = tid + u * 256;
            int row = s >> 3, col = (s & 7) * 8;
            cp_async16(kb0 + (uint32_t)(KBUF + row * SST + col) * 2,
                       Kb + (size_t)(b * Sz + 64 + row) * ldqk + h * DHz + col);
        }
    }
    CP_COMMIT();

    float psum[2][2] = {};
    const int npairs = (it + 2) >> 1;

    // ---------------- pass 1: S, exp, P -> smem ----------------
    for (int p = 0; p < npairs; p++) {
        CP_WAIT(0);
        __syncthreads();
        int nk = (p + 1) * 2;
        if (nk <= it) {
            uint32_t nb = kb0 + (uint32_t)((((p + 1) & 1) * 2) * KBUF) * 2;
            #pragma unroll
            for (int u = 0; u < 2; u++) {
                int s = tid + u * 256;
                int row = s >> 3, col = (s & 7) * 8;
                cp_async16(nb + (uint32_t)(row * SST + col) * 2,
                           Kb + (size_t)(b * Sz + nk * 64 + row) * ldqk
                               + h * DHz + col);
            }
            if (nk + 1 <= it) {
                #pragma unroll
                for (int u = 0; u < 2; u++) {
                    int s = tid + u * 256;
                    int row = s >> 3, col = (s & 7) * 8;
                    cp_async16(nb + (uint32_t)(KBUF + row * SST + col) * 2,
                               Kb + (size_t)(b * Sz + (nk + 1) * 64 + row) * ldqk
                                   + h * DHz + col);
                }
            }
            CP_COMMIT();
        }

        int t = 2 * p + (warp_n >> 1);          // this warp's kt tile
        if (t <= it) {
            uint32_t kb = kb0 +
                (uint32_t)((((p & 1) * 2 + (warp_n >> 1)) * KBUF) * 2);
            int colbase = (warp_n & 1) * 32;    // within tile

            float accS[2][4][4] = {};
            #pragma unroll
            for (int ks = 0; ks < 4; ks++) {
                int kc = ks * 16;
                uint32_t af[2][4];
                #pragma unroll
                for (int im = 0; im < 2; im++) {
                    int row = warp_m * 32 + im * 16 + a_row_off;
                    ldm_x4(af[im], qb + (uint32_t)(row * SST + kc + a_col_off) * 2);
                }
                uint32_t bf[2][4];
                #pragma unroll
                for (int bg = 0; bg < 2; bg++) {
                    int row = colbase + bg * 16 + b_row_off;
                    ldm_x4(bf[bg], kb + (uint32_t)(row * SST + kc + b_col_off) * 2);
                }
                #pragma unroll
                for (int im = 0; im < 2; im++)
                    #pragma unroll
                    for (int bg = 0; bg < 2; bg++) {
                        mma_f16(accS[im][bg * 2 + 0], af[im], bf[bg][0], bf[bg][1]);
                        mma_f16(accS[im][bg * 2 + 1], af[im], bf[bg][2], bf[bg][3]);
                    }
            }

            int diag = (t == it);
            #pragma unroll
            for (int im = 0; im < 2; im++) {
                int r0 = warp_m * 32 + im * 16 + lg;
                int g0 = it * 64 + r0, g1 = g0 + 8;
                #pragma unroll
                for (int nt = 0; nt < 4; nt++) {
                    int gc = t * 64 + colbase + nt * 8 + 2 * lq;
                    float p00 = __expf(accS[im][nt][0] * 0.125f);
                    float p01 = __expf(accS[im][nt][1] * 0.125f);
                    float p10 = __expf(accS[im][nt][2] * 0.125f);
                    float p11 = __expf(accS[im][nt][3] * 0.125f);
                    if (diag) {
                        if (gc     > g0) p00 = 0.f;
                        if (gc + 1 > g0) p01 = 0.f;
                        if (gc     > g1) p10 = 0.f;
                        if (gc + 1 > g1) p11 = 0.f;
                    }
                    psum[im][0] += p00 + p01;
                    psum[im][1] += p10 + p11;
                    *(__half2*)&Ps[r0 * PST + gc]       = __floats2half2_rn(p00, p01);
                    *(__half2*)&Ps[(r0 + 8) * PST + gc] = __floats2half2_rn(p10, p11);
                }
            }
        }
    }

    __syncthreads();   // Ps complete; K buffer reads done

    // prefetch V pair 0 into buffers 0,1
    #pragma unroll
    for (int u = 0; u < 2; u++) {
        int s = tid + u * 256;
        int row = s >> 3, col = (s & 7) * 8;
        cp_async16(kb0 + (uint32_t)(row * SST + col) * 2,
                   V + (size_t)(b * Sz + row) * ldqk + h * DHz + col);
    }
    if (it >= 1) {
        #pragma unroll
        for (int u = 0; u < 2; u++) {
            int s = tid + u * 256;
            int row = s >> 3, col = (s & 7) * 8;
            cp_async16(kb0 + (uint32_t)(KBUF + row * SST + col) * 2,
                       V + (size_t)(b * Sz + 64 + row) * ldqk + h * DHz + col);
        }
    }
    CP_COMMIT();

    // row-sum reduce -> linv
    #pragma unroll
    for (int im = 0; im < 2; im++)
        #pragma unroll
        for (int rh = 0; rh < 2; rh++) {
            float v = psum[im][rh];
            v += __shfl_xor_sync(0xffffffff, v, 1);
            v += __shfl_xor_sync(0xffffffff, v, 2);
            if (lq == 0) {
                int row = warp_m * 32 + im * 16 + lg + rh * 8;
                red[warp_n * 64 + row] = v;
            }
        }
    __syncthreads();
    if (tid < 64) {
        float l = red[tid] + red[64 + tid] + red[128 + tid] + red[192 + tid];
        linv[tid] = 1.f / l;
    }
    __syncthreads();

    // ---------------- pass 2: O = P @ V (paired tiles) ----------------
    float accO[2][2][4] = {};
    for (int p = 0; p < npairs; p++) {
        CP_WAIT(0);
        __syncthreads();
        int nk = (p + 1) * 2;
        if (nk <= it) {
            uint32_t nb = kb0 + (uint32_t)((((p + 1) & 1) * 2) * KBUF) * 2;
            #pragma unroll
            for (int u = 0; u < 2; u++) {
                int s = tid + u * 256;
                int row = s >> 3, col = (s & 7) * 8;
                cp_async16(nb + (uint32_t)(row * SST + col) * 2,
                           V + (size_t)(b * Sz + nk * 64 + row) * ldqk
                               + h * DHz + col);
            }
            if (nk + 1 <= it) {
                #pragma unroll
                for (int u = 0; u < 2; u++) {
                    int s = tid + u * 256;
                    int row = s >> 3, col = (s & 7) * 8;
                    cp_async16(nb + (uint32_t)(KBUF + row * SST + col) * 2,
                               V + (size_t)(b * Sz + (nk + 1) * 64 + row) * ldqk
                                   + h * DHz + col);
                }
            }
            CP_COMMIT();
        }

        #pragma unroll
        for (int tt = 0; tt < 2; tt++) {
            int kt = 2 * p + tt;
            if (kt > it) break;
            uint32_t vb = kb0 + (uint32_t)((((p & 1) * 2 + tt) * KBUF) * 2);

            #pragma unroll
            for (int ks = 0; ks < 4; ks++) {
                int kc = kt * 64 + ks * 16;
                uint32_t af[2][4];
                #pragma unroll
                for (int im = 0; im < 2; im++) {
                    int row = warp_m * 32 + im * 16 + a_row_off;
                    ldm_x4(af[im], pb + (uint32_t)(row * PST + kc + a_col_off) * 2);
                }
                uint32_t bf[4];
                {
                    int krow = ks * 16 + bt_row_off;
                    int ncol = warp_n * 16 + bt_col_off;
                    ldm_x4_trans(bf, vb + (uint32_t)(krow * SST + ncol) * 2);
                }
                #pragma unroll
                for (int im = 0; im < 2; im++) {
                    mma_f16(accO[im][0], af[im], bf[0], bf[1]);
                    mma_f16(accO[im][1], af[im], bf[2], bf[3]);
                }
            }
        }
    }

    // ctx write (normalized)
    #pragma unroll
    for (int im = 0; im < 2; im++) {
        int r0 = warp_m * 32 + im * 16 + lg;
        float il0 = linv[r0], il1 = linv[r0 + 8];
        int gr = it * 64 + r0;
        #pragma unroll
        for (int nt = 0; nt < 2; nt++) {
            int d = warp_n * 16 + nt * 8 + 2 * lq;
            __half* p0 = ctxh + ((size_t)(b * Sz) + gr) * Dz + h * DHz + d;
            __half* p1 = p0 + (size_t)8 * Dz;
            *(__half2*)p0 = __floats2half2_rn(accO[im][nt][0] * il0,
                                              accO[im][nt][1] * il0);
            *(__half2*)p1 = __floats2half2_rn(accO[im][nt][2] * il1,
                                              accO[im][nt][3] * il1);
        }
    }

    // attn write
    for (int j = 0; j < 64; j++) {
        int grow = it * 64 + j;
        int limit = grow + 1;
        float il = linv[j];
        int col = tid * 4;
        float4 o;
        o.x = (col     < limit) ? __half2float(Ps[j * PST + col])     * il : 0.f;
        o.y = (col + 1 < limit) ? __half2float(Ps[j * PST + col + 1]) * il : 0.f;
        o.z = (col + 2 < limit) ? __half2float(Ps[j * PST + col + 2]) * il : 0.f;
        o.w = (col + 3 < limit) ? __half2float(Ps[j * PST + col + 3]) * il : 0.f;
        *(float4*)(attn + ((size_t)bh * Sz + grow) * Sz + col) = o;
    }
}

// ===================== residual + LayerNorm (fp32, optional half out) =======
__global__ __launch_bounds__(256) void add_ln_kernel(
    const float* __restrict__ x, const float* __restrict__ r,
    const float* __restrict__ g, const float* __restrict__ be,
    float* __restrict__ out, __half* __restrict__ outh)
{
    int row = blockIdx.x;
    const float* xr = x + (size_t)row * Dz;
    const float* rr = r + (size_t)row * Dz;
    float* orow = out + (size_t)row * Dz;
    int tid = threadIdx.x;

    float v[4];
    float lsum = 0.f, lsq = 0.f;
    #pragma unroll
    for (int u = 0; u < 4; u++) {
        int c = tid + u * 256;
        v[u] = xr[c] + rr[c];
        lsum += v[u];
        lsq  += v[u] * v[u];
    }

    __shared__ float s1[256], s2[256];
    s1[tid] = lsum; s2[tid] = lsq;
    __syncthreads();
    #pragma unroll
    for (int s = 128; s > 0; s >>= 1) {
        if (tid < s) { s1[tid] += s1[tid + s]; s2[tid] += s2[tid + s]; }
        __syncthreads();
    }
    float mean = s1[0] * (1.f / Dz);
    float var  = s2[0] * (1.f / Dz) - mean * mean;
    float inv  = rsqrtf(var + 1e-5f);

    #pragma unroll
    for (int u = 0; u < 4; u++) {
        int c = tid + u * 256;
        float o = (v[u] - mean) * inv * g[c] + be[c];
        orow[c] = o;
        if (outh) outh[(size_t)row * Dz + c] = __float2half_rn(o);
    }
}

// ===================== host launch ==========================================
extern "C" void kernel_launch(void* const* d_in, const int* in_sizes, int n_in,
                              void* d_out, int out_size)
{
    const float* x    = (const float*)d_in[0];
    const float* Wq   = (const float*)d_in[1];
    const float* bq   = (const float*)d_in[2];
    const float* Wk   = (const float*)d_in[3];
    const float* bk   = (const float*)d_in[4];
    const float* Wv   = (const float*)d_in[5];
    const float* bv   = (const float*)d_in[6];
    const float* Wo   = (const float*)d_in[7];
    const float* bo   = (const float*)d_in[8];
    const float* ln1g = (const float*)d_in[9];
    const float* ln1b = (const float*)d_in[10];
    const float* W1   = (const float*)d_in[11];
    const float* b1   = (const float*)d_in[12];
    const float* W2   = (const float*)d_in[13];
    const float* b2   = (const float*)d_in[14];
    const float* ln2g = (const float*)d_in[15];
    const float* ln2b = (const float*)d_in[16];

    float* out  = (float*)d_out;
    float* y    = out;
    float* attn = out + (size_t)BSz * Dz;

    float *t1, *h, *bqkv;
    __half *xh, *qkvh, *ctxh, *hh, *ffh;
    __half *wqkvh, *woh, *w1h, *w2h;
    cudaGetSymbolAddress((void**)&t1,   g_t1);
    cudaGetSymbolAddress((void**)&h,    g_h);
    cudaGetSymbolAddress((void**)&bqkv, g_bqkv);
    cudaGetSymbolAddress((void**)&xh,   g_xh);
    cudaGetSymbolAddress((void**)&qkvh, g_qkvh);
    cudaGetSymbolAddress((void**)&ctxh, g_ctxh);
    cudaGetSymbolAddress((void**)&hh,   g_hh);
    cudaGetSymbolAddress((void**)&ffh,  g_ffh);
    cudaGetSymbolAddress((void**)&wqkvh, g_wqkvh);
    cudaGetSymbolAddress((void**)&woh,  g_woh);
    cudaGetSymbolAddress((void**)&w1h,  g_w1h);
    cudaGetSymbolAddress((void**)&w2h,  g_w2h);

    cudaFuncSetAttribute(hgemm_kernel,
                         cudaFuncAttributeMaxDynamicSharedMemorySize, GEMM_SMEM);
    cudaFuncSetAttribute(attn_fused_kernel,
                         cudaFuncAttributeMaxDynamicSharedMemorySize, ATT_SMEM);

    static cudaStream_t s2 = nullptr;
    static cudaEvent_t evFork = nullptr, evJoin = nullptr;
    if (s2 == nullptr) {
        cudaStreamCreateWithFlags(&s2, cudaStreamNonBlocking);
        cudaEventCreateWithFlags(&evFork, cudaEventDisableTiming);
        cudaEventCreateWithFlags(&evJoin, cudaEventDisableTiming);
    }

    const __half* qh = qkvh;
    const __half* kh = qkvh + Dz;
    const __half* vh = qkvh + 2 * Dz;

    dim3 tDD(Dz / 32, Dz / 32);
    dim3 gQKV(QKVN / GBN, BSz / GBM);   // 12 x 32 = 384 CTAs
    dim3 gDD(Dz / GBN, BSz / GBM);      // 4 x 32 = 128 CTAs
    dim3 gDF(FFz / GBN, BSz / GBM);     // 16 x 32 = 512 CTAs

    Ptr3 wsrc; wsrc.p[0] = Wq; wsrc.p[1] = Wk; wsrc.p[2] = Wv;

    // fork side stream: Wo/W1/W2 transposes overlap the main chain
    cudaEventRecord(evFork, 0);
    cudaStreamWaitEvent(s2, evFork, 0);
    transpose_half_kernel<<<dim3(FFz / 32, Dz / 32), 256, 0, s2>>>(W1, w1h, Dz, FFz);
    transpose_half_kernel<<<tDD, 256, 0, s2>>>(Wo, woh, Dz, Dz);
    transpose_half_kernel<<<dim3(Dz / 32, FFz / 32), 256, 0, s2>>>(W2, w2h, FFz, Dz);
    cudaEventRecord(evJoin, s2);

    // main chain
    cvt_half_kernel<<<(BSz * Dz) / 1024, 256>>>(x, xh);
    transpose_qkv_kernel<<<dim3(Dz / 32, Dz / 32, 3), 256>>>(wsrc, wqkvh);
    bias_concat_kernel<<<QKVN / 256, 256>>>(bq, bk, bv, bqkv);
    hgemm_kernel<<<gQKV, 512, GEMM_SMEM>>>(xh, wqkvh, bqkv, nullptr, qkvh,
                                           BSz, QKVN, Dz, 0);

    attn_fused_kernel<<<dim3(Sz / 64, BHz), 256, ATT_SMEM>>>(
        qh, kh, vh, QKVN, attn, ctxh);

    cudaStreamWaitEvent(0, evJoin, 0);
    hgemm_kernel<<<gDD, 512, GEMM_SMEM>>>(ctxh, woh, bo, t1, nullptr,
                                          BSz, Dz, Dz, 0);
    add_ln_kernel<<<BSz, 256>>>(x, t1, ln1g, ln1b, h, hh);
    hgemm_kernel<<<gDF, 512, GEMM_SMEM>>>(hh, w1h, b1, nullptr, ffh,
                                          BSz, FFz, Dz, 1);
    hgemm_kernel<<<gDD, 512, GEMM_SMEM>>>(ffh, w2h, b2, t1, nullptr,
                                          BSz, Dz, FFz, 0);
    add_ln_kernel<<<BSz, 256>>>(h, t1, ln2g, ln2b, y, nullptr);
}

// round 16
// speedup vs baseline: 1.3375x; 1.0298x over previous
#include <cuda_runtime.h>
#include <cuda_fp16.h>
#include <math.h>
#include <stdint.h>

#define Bz 4
#define Sz 1024
#define Dz 1024
#define Hz 16
#define DHz 64
#define FFz 4096
#define BSz (Bz*Sz)      // 4096
#define BHz (Bz*Hz)      // 64
#define QKVN (3*Dz)      // 3072

// ===================== scratch ==============================================
__device__ float  g_t1 [BSz*Dz];      // attn_out, then ff2 (fp32 residual)
__device__ float  g_h  [BSz*Dz];      // h (fp32)
__device__ float  g_bqkv[QKVN];       // concat bias
__device__ __half g_xh  [BSz*Dz];
__device__ __half g_qkvh[(size_t)BSz*QKVN];   // fused q|k|v, row stride 3072
__device__ __half g_ctxh[BSz*Dz];
__device__ __half g_hh  [BSz*Dz];
__device__ __half g_ffh [BSz*FFz];
__device__ __half g_wqkvh[(size_t)QKVN*Dz];   // [3072][1024] = WqT|WkT|WvT
__device__ __half g_woh [Dz*Dz];
__device__ __half g_w1h [(size_t)Dz*FFz];
__device__ __half g_w2h [(size_t)Dz*FFz];

// ===================== helpers ==============================================
__device__ __forceinline__ uint32_t smem_u32(const void* p) {
    uint32_t a;
    asm("{ .reg .u64 t; cvta.to.shared.u64 t, %1; cvt.u32.u64 %0, t; }"
        : "=r"(a) : "l"(p));
    return a;
}
__device__ __forceinline__ void cp_async16(uint32_t dst, const void* src) {
    asm volatile("cp.async.cg.shared.global [%0], [%1], 16;"
                 :: "r"(dst), "l"(src));
}
#define CP_COMMIT() asm volatile("cp.async.commit_group;" ::: "memory")
#define CP_WAIT(n)  asm volatile("cp.async.wait_group %0;" :: "n"(n) : "memory")

__device__ __forceinline__ void ldm_x4(uint32_t* r, uint32_t addr) {
    asm volatile("ldmatrix.sync.aligned.m8n8.x4.shared.b16 {%0,%1,%2,%3}, [%4];"
                 : "=r"(r[0]), "=r"(r[1]), "=r"(r[2]), "=r"(r[3]) : "r"(addr));
}
__device__ __forceinline__ void ldm_x4_trans(uint32_t* r, uint32_t addr) {
    asm volatile("ldmatrix.sync.aligned.m8n8.x4.trans.shared.b16 {%0,%1,%2,%3}, [%4];"
                 : "=r"(r[0]), "=r"(r[1]), "=r"(r[2]), "=r"(r[3]) : "r"(addr));
}
__device__ __forceinline__ void mma_f16(float* c, const uint32_t* a,
                                        uint32_t b0, uint32_t b1) {
    asm volatile(
        "mma.sync.aligned.m16n8k16.row.col.f32.f16.f16.f32 "
        "{%0,%1,%2,%3}, {%4,%5,%6,%7}, {%8,%9}, {%0,%1,%2,%3};"
        : "+f"(c[0]), "+f"(c[1]), "+f"(c[2]), "+f"(c[3])
        : "r"(a[0]), "r"(a[1]), "r"(a[2]), "r"(a[3]), "r"(b0), "r"(b1));
}

// ===================== batched weight transpose (QKV) =======================
struct Ptr3 { const float* p[3]; };
__global__ __launch_bounds__(256) void transpose_qkv_kernel(
    Ptr3 srcs, __half* __restrict__ out)
{
    __shared__ float t[32][33];
    int z = blockIdx.z;
    const float* in = srcs.p[z];
    __half* o = out + (size_t)z * Dz * Dz;
    int c0 = blockIdx.x * 32, r0 = blockIdx.y * 32;
    int x = threadIdx.x & 31, y = threadIdx.x >> 5;
    #pragma unroll
    for (int u = 0; u < 4; u++)
        t[y + 8 * u][x] = in[(size_t)(r0 + y + 8 * u) * Dz + c0 + x];
    __syncthreads();
    #pragma unroll
    for (int u = 0; u < 4; u++)
        o[(size_t)(c0 + y + 8 * u) * Dz + r0 + x] = __float2half_rn(t[x][y + 8 * u]);
}

// ===================== generic weight transpose =============================
__global__ __launch_bounds__(256) void transpose_half_kernel(
    const float* __restrict__ in, __half* __restrict__ out, int R, int C)
{
    __shared__ float t[32][33];
    int c0 = blockIdx.x * 32, r0 = blockIdx.y * 32;
    int x = threadIdx.x & 31, y = threadIdx.x >> 5;
    #pragma unroll
    for (int u = 0; u < 4; u++)
        t[y + 8 * u][x] = in[(size_t)(r0 + y + 8 * u) * C + c0 + x];
    __syncthreads();
    #pragma unroll
    for (int u = 0; u < 4; u++)
        out[(size_t)(c0 + y + 8 * u) * R + r0 + x] = __float2half_rn(t[x][y + 8 * u]);
}

// ===================== bias concat ==========================================
__global__ __launch_bounds__(256) void bias_concat_kernel(
    const float* __restrict__ bq, const float* __restrict__ bk,
    const float* __restrict__ bv, float* __restrict__ o)
{
    int i = blockIdx.x * 256 + threadIdx.x;
    float v = (i < Dz) ? bq[i] : (i < 2 * Dz) ? bk[i - Dz] : bv[i - 2 * Dz];
    o[i] = v;
}

// ===================== cvt copy: out_h = half(in) ===========================
__global__ __launch_bounds__(256) void cvt_half_kernel(
    const float* __restrict__ in, __half* __restrict__ out)
{
    size_t i = ((size_t)blockIdx.x * 256 + threadIdx.x) * 4;
    float4 v = *(const float4*)(in + i);
    __half2* o = (__half2*)(out + i);
    o[0] = __floats2half2_rn(v.x, v.y);
    o[1] = __floats2half2_rn(v.z, v.w);
}

// ===================== FP16 mma GEMM: 128x256x64, 512 thr, 3-stage ==========
#define GBM 128
#define GBN 256
#define GBK 64
#define KST2 72
#define STG_A 18432
#define STG_BYTES 55296
#define NSTAGE 3
#define GEMM_SMEM (NSTAGE * STG_BYTES)   // 165888

__global__ __launch_bounds__(512) void hgemm_kernel(
    const __half* __restrict__ A, const __half* __restrict__ Bt,
    const float* __restrict__ bias, float* __restrict__ Cf,
    __half* __restrict__ Ch, int M, int N, int K, int relu)
{
    extern __shared__ __half hsm[];
    uint32_t sbase = smem_u32(hsm);
    int tid = threadIdx.x;
    int wid = tid >> 5, lane = tid & 31;
    int m0 = blockIdx.y * GBM, n0 = blockIdx.x * GBN;
    int warp_m = wid >> 3, warp_n = wid & 7;
    int lg = lane >> 2, lq = lane & 3;

    float acc[4][4][4] = {};

    int row0 = tid >> 3, col0 = (tid & 7) * 8;
    uint32_t offA = (uint32_t)(row0 * KST2 + col0) * 2;
    const __half* Ap = A  + (size_t)(m0 + row0) * K + col0;
    const __half* Bp = Bt + (size_t)(n0 + row0) * K + col0;
    const size_t K64 = (size_t)64 * K;

    const int nchunks = K / GBK;

    #pragma unroll
    for (int pc = 0; pc < 2; pc++) {
        uint32_t base = sbase + (uint32_t)pc * STG_BYTES;
        size_t koff = (size_t)pc * GBK;
        cp_async16(base + offA,                 Ap + koff);
        cp_async16(base + offA + 64*KST2*2,     Ap + koff + K64);
        uint32_t bb = base + STG_A + offA;
        cp_async16(bb,                  Bp + koff);
        cp_async16(bb + 64*KST2*2,      Bp + koff + K64);
        cp_async16(bb + 128*KST2*2,     Bp + koff + 2*K64);
        cp_async16(bb + 192*KST2*2,     Bp + koff + 3*K64);
        CP_COMMIT();
    }

    int a_row_off = (lane & 7) + ((lane & 8) ? 8 : 0);
    int a_col_off = (lane & 16) ? 8 : 0;
    int b_row_off = (lane & 7) + ((lane & 16) ? 8 : 0);
    int b_col_off = (lane & 8) ? 8 : 0;

    for (int c = 0; c < nchunks; c++) {
        CP_WAIT(1);
        __syncthreads();

        if (c + 2 < nchunks) {
            uint32_t base = sbase + (uint32_t)((c + 2) % NSTAGE) * STG_BYTES;
            size_t koff = (size_t)(c + 2) * GBK;
            cp_async16(base + offA,                 Ap + koff);
            cp_async16(base + offA + 64*KST2*2,     Ap + koff + K64);
            uint32_t bb = base + STG_A + offA;
            cp_async16(bb,                  Bp + koff);
            cp_async16(bb + 64*KST2*2,      Bp + koff + K64);
            cp_async16(bb + 128*KST2*2,     Bp + koff + 2*K64);
            cp_async16(bb + 192*KST2*2,     Bp + koff + 3*K64);
        }
        CP_COMMIT();

        uint32_t abase = sbase + (uint32_t)(c % NSTAGE) * STG_BYTES;
        uint32_t bbase = abase + STG_A;

        #pragma unroll
        for (int ks = 0; ks < 4; ks++) {
            int kc = ks * 16;
            uint32_t af[4][4];
            #pragma unroll
            for (int im = 0; im < 4; im++) {
                int row = warp_m * 64 + im * 16 + a_row_off;
                ldm_x4(af[im], abase + (uint32_t)(row * KST2 + kc + a_col_off) * 2);
            }
            uint32_t bf[2][4];
            #pragma unroll
            for (int pr = 0; pr < 2; pr++) {
                int row = warp_n * 32 + pr * 16 + b_row_off;
                ldm_x4(bf[pr], bbase + (uint32_t)(row * KST2 + kc + b_col_off) * 2);
            }
            #pragma unroll
            for (int im = 0; im < 4; im++)
                #pragma unroll
                for (int pr = 0; pr < 2; pr++) {
                    mma_f16(acc[im][pr * 2 + 0], af[im], bf[pr][0], bf[pr][1]);
                    mma_f16(acc[im][pr * 2 + 1], af[im], bf[pr][2], bf[pr][3]);
                }
        }
    }

    #pragma unroll
    for (int im = 0; im < 4; im++) {
        int r0 = m0 + warp_m * 64 + im * 16 + lg;
        #pragma unroll
        for (int nt = 0; nt < 4; nt++) {
            int cc = n0 + warp_n * 32 + nt * 8 + 2 * lq;
            float b0 = bias[cc], b1 = bias[cc + 1];
            float v00 = acc[im][nt][0] + b0, v01 = acc[im][nt][1] + b1;
            float v10 = acc[im][nt][2] + b0, v11 = acc[im][nt][3] + b1;
            if (relu) {
                v00 = fmaxf(v00, 0.f); v01 = fmaxf(v01, 0.f);
                v10 = fmaxf(v10, 0.f); v11 = fmaxf(v11, 0.f);
            }
            if (Cf) {
                float2 a2; a2.x = v00; a2.y = v01;
                float2 b2; b2.x = v10; b2.y = v11;
                *(float2*)(Cf + (size_t)r0 * N + cc) = a2;
                *(float2*)(Cf + (size_t)(r0 + 8) * N + cc) = b2;
            }
            if (Ch) {
                *(__half2*)(Ch + (size_t)r0 * N + cc) = __floats2half2_rn(v00, v01);
                *(__half2*)(Ch + (size_t)(r0 + 8) * N + cc) = __floats2half2_rn(v10, v11);
            }
        }
    }
}

// ===================== fused attention (paired kt tiles) ====================
#define SST 72           // Q/K/V tile row stride (halfs)
#define PST 1032         // P row stride in halfs
#define KBUF (64 * SST)  // halfs per K/V buffer
#define ATT_SMEM 179456

__global__ __launch_bounds__(256) void attn_fused_kernel(
    const __half* __restrict__ Q, const __half* __restrict__ Kb,
    const __half* __restrict__ V, int ldqk,
    float* __restrict__ attn, __half* __restrict__ ctxh)
{
    extern __shared__ char asmem[];
    __half* Qs = (__half*)asmem;
    __half* Ks = Qs + 64 * SST;
    __half* Ps = Ks + 4 * KBUF;
    float* red  = (float*)(Ps + 64 * PST);
    float* linv = red + 256;
    uint32_t qb  = smem_u32(Qs);
    uint32_t kb0 = smem_u32(Ks);
    uint32_t pb  = smem_u32(Ps);

    int it = 15 - (int)blockIdx.x;
    int bh = blockIdx.y;
    int b = bh / Hz, h = bh % Hz;
    int tid = threadIdx.x, wid = tid >> 5, lane = tid & 31;
    int lg = lane >> 2, lq = lane & 3;
    int warp_m = wid >> 2, warp_n = wid & 3;
    int a_row_off = (lane & 7) + ((lane & 8) ? 8 : 0);
    int a_col_off = (lane & 16) ? 8 : 0;
    int b_row_off = (lane & 7) + ((lane & 16) ? 8 : 0);
    int b_col_off = (lane & 8) ? 8 : 0;
    int bt_row_off = (lane & 7) + ((lane & 8) ? 8 : 0);
    int bt_col_off = (lane & 16) ? 8 : 0;

    #pragma unroll
    for (int u = 0; u < 2; u++) {
        int s = tid + u * 256;
        int row = s >> 3, col = (s & 7) * 8;
        cp_async16(qb + (uint32_t)(row * SST + col) * 2,
                   Q + (size_t)(b * Sz + it * 64 + row) * ldqk + h * DHz + col);
    }
    CP_COMMIT();
    #pragma unroll
    for (int u = 0; u < 2; u++) {
        int s = tid + u * 256;
        int row = s >> 3, col = (s & 7) * 8;
        cp_async16(kb0 + (uint32_t)(row * SST + col) * 2,
                   Kb + (size_t)(b * Sz + row) * ldqk + h * DHz + col);
    }
    if (it >= 1) {
        #pragma unroll
        for (int u = 0; u < 2; u++) {
            int s = tid + u * 256;
            int row = s >> 3, col = (s & 7) * 8;
            cp_async16(kb0 + (uint32_t)(KBUF + row * SST + col) * 2,
                       Kb + (size_t)(b * Sz + 64 + row) * ldqk + h * DHz + col);
        }
    }
    CP_COMMIT();

    float psum[2][2] = {};
    const int npairs = (it + 2) >> 1;

    // ---------------- pass 1 ----------------
    for (int p = 0; p < npairs; p++) {
        CP_WAIT(0);
        __syncthreads();
        int nk = (p + 1) * 2;
        if (nk <= it) {
            uint32_t nb = kb0 + (uint32_t)((((p + 1) & 1) * 2) * KBUF) * 2;
            #pragma unroll
            for (int u = 0; u < 2; u++) {
                int s = tid + u * 256;
                int row = s >> 3, col = (s & 7) * 8;
                cp_async16(nb + (uint32_t)(row * SST + col) * 2,
                           Kb + (size_t)(b * Sz + nk * 64 + row) * ldqk
                               + h * DHz + col);
            }
            if (nk + 1 <= it) {
                #pragma unroll
                for (int u = 0; u < 2; u++) {
                    int s = tid + u * 256;
                    int row = s >> 3, col = (s & 7) * 8;
                    cp_async16(nb + (uint32_t)(KBUF + row * SST + col) * 2,
                               Kb + (size_t)(b * Sz + (nk + 1) * 64 + row) * ldqk
                                   + h * DHz + col);
                }
            }
            CP_COMMIT();
        }

        int t = 2 * p + (warp_n >> 1);
        if (t <= it) {
            uint32_t kb = kb0 +
                (uint32_t)((((p & 1) * 2 + (warp_n >> 1)) * KBUF) * 2);
            int colbase = (warp_n & 1) * 32;

            float accS[2][4][4] = {};
            #pragma unroll
            for (int ks = 0; ks < 4; ks++) {
                int kc = ks * 16;
                uint32_t af[2][4];
                #pragma unroll
                for (int im = 0; im < 2; im++) {
                    int row = warp_m * 32 + im * 16 + a_row_off;
                    ldm_x4(af[im], qb + (uint32_t)(row * SST + kc + a_col_off) * 2);
                }
                uint32_t bf[2][4];
                #pragma unroll
                for (int bg = 0; bg < 2; bg++) {
                    int row = colbase + bg * 16 + b_row_off;
                    ldm_x4(bf[bg], kb + (uint32_t)(row * SST + kc + b_col_off) * 2);
                }
                #pragma unroll
                for (int im = 0; im < 2; im++)
                    #pragma unroll
                    for (int bg = 0; bg < 2; bg++) {
                        mma_f16(accS[im][bg * 2 + 0], af[im], bf[bg][0], bf[bg][1]);
                        mma_f16(accS[im][bg * 2 + 1], af[im], bf[bg][2], bf[bg][3]);
                    }
            }

            int diag = (t == it);
            #pragma unroll
            for (int im = 0; im < 2; im++) {
                int r0 = warp_m * 32 + im * 16 + lg;
                int g0 = it * 64 + r0, g1 = g0 + 8;
                #pragma unroll
                for (int nt = 0; nt < 4; nt++) {
                    int gc = t * 64 + colbase + nt * 8 + 2 * lq;
                    float p00 = __expf(accS[im][nt][0] * 0.125f);
                    float p01 = __expf(accS[im][nt][1] * 0.125f);
                    float p10 = __expf(accS[im][nt][2] * 0.125f);
                    float p11 = __expf(accS[im][nt][3] * 0.125f);
                    if (diag) {
                        if (gc     > g0) p00 = 0.f;
                        if (gc + 1 > g0) p01 = 0.f;
                        if (gc     > g1) p10 = 0.f;
                        if (gc + 1 > g1) p11 = 0.f;
                    }
                    psum[im][0] += p00 + p01;
                    psum[im][1] += p10 + p11;
                    *(__half2*)&Ps[r0 * PST + gc]       = __floats2half2_rn(p00, p01);
                    *(__half2*)&Ps[(r0 + 8) * PST + gc] = __floats2half2_rn(p10, p11);
                }
            }
        }
    }

    __syncthreads();

    // prefetch V pair 0
    #pragma unroll
    for (int u = 0; u < 2; u++) {
        int s = tid + u * 256;
        int row = s >> 3, col = (s & 7) * 8;
        cp_async16(kb0 + (uint32_t)(row * SST + col) * 2,
                   V + (size_t)(b * Sz + row) * ldqk + h * DHz + col);
    }
    if (it >= 1) {
        #pragma unroll
        for (int u = 0; u < 2; u++) {
            int s = tid + u * 256;
            int row = s >> 3, col = (s & 7) * 8;
            cp_async16(kb0 + (uint32_t)(KBUF + row * SST + col) * 2,
                       V + (size_t)(b * Sz + 64 + row) * ldqk + h * DHz + col);
        }
    }
    CP_COMMIT();

    // row-sum reduce -> linv
    #pragma unroll
    for (int im = 0; im < 2; im++)
        #pragma unroll
        for (int rh = 0; rh < 2; rh++) {
            float v = psum[im][rh];
            v += __shfl_xor_sync(0xffffffff, v, 1);
            v += __shfl_xor_sync(0xffffffff, v, 2);
            if (lq == 0) {
                int row = warp_m * 32 + im * 16 + lg + rh * 8;
                red[warp_n * 64 + row] = v;
            }
        }
    __syncthreads();
    if (tid < 64) {
        float l = red[tid] + red[64 + tid] + red[128 + tid] + red[192 + tid];
        linv[tid] = 1.f / l;
    }
    __syncthreads();

    // ---------------- pass 2 ----------------
    float accO[2][2][4] = {};
    for (int p = 0; p < npairs; p++) {
        CP_WAIT(0);
        __syncthreads();
        int nk = (p + 1) * 2;
        if (nk <= it) {
            uint32_t nb = kb0 + (uint32_t)((((p + 1) & 1) * 2) * KBUF) * 2;
            #pragma unroll
            for (int u = 0; u < 2; u++) {
                int s = tid + u * 256;
                int row = s >> 3, col = (s & 7) * 8;
                cp_async16(nb + (uint32_t)(row * SST + col) * 2,
                           V + (size_t)(b * Sz + nk * 64 + row) * ldqk
                               + h * DHz + col);
            }
            if (nk + 1 <= it) {
                #pragma unroll
                for (int u = 0; u < 2; u++) {
                    int s = tid + u * 256;
                    int row = s >> 3, col = (s & 7) * 8;
                    cp_async16(nb + (uint32_t)(KBUF + row * SST + col) * 2,
                               V + (size_t)(b * Sz + (nk + 1) * 64 + row) * ldqk
                                   + h * DHz + col);
                }
            }
            CP_COMMIT();
        }

        #pragma unroll
        for (int tt = 0; tt < 2; tt++) {
            int kt = 2 * p + tt;
            if (kt > it) break;
            uint32_t vb = kb0 + (uint32_t)((((p & 1) * 2 + tt) * KBUF) * 2);

            #pragma unroll
            for (int ks = 0; ks < 4; ks++) {
                int kc = kt * 64 + ks * 16;
                uint32_t af[2][4];
                #pragma unroll
                for (int im = 0; im < 2; im++) {
                    int row = warp_m * 32 + im * 16 + a_row_off;
                    ldm_x4(af[im], pb + (uint32_t)(row * PST + kc + a_col_off) * 2);
                }
                uint32_t bf[4];
                {
                    int krow = ks * 16 + bt_row_off;
                    int ncol = warp_n * 16 + bt_col_off;
                    ldm_x4_trans(bf, vb + (uint32_t)(krow * SST + ncol) * 2);
                }
                #pragma unroll
                for (int im = 0; im < 2; im++) {
                    mma_f16(accO[im][0], af[im], bf[0], bf[1]);
                    mma_f16(accO[im][1], af[im], bf[2], bf[3]);
                }
            }
        }
    }

    // ctx write (normalized)
    #pragma unroll
    for (int im = 0; im < 2; im++) {
        int r0 = warp_m * 32 + im * 16 + lg;
        float il0 = linv[r0], il1 = linv[r0 + 8];
        int gr = it * 64 + r0;
        #pragma unroll
        for (int nt = 0; nt < 2; nt++) {
            int d = warp_n * 16 + nt * 8 + 2 * lq;
            __half* p0 = ctxh + ((size_t)(b * Sz) + gr) * Dz + h * DHz + d;
            __half* p1 = p0 + (size_t)8 * Dz;
            *(__half2*)p0 = __floats2half2_rn(accO[im][nt][0] * il0,
                                              accO[im][nt][1] * il0);
            *(__half2*)p1 = __floats2half2_rn(accO[im][nt][2] * il1,
                                              accO[im][nt][3] * il1);
        }
    }

    // attn write
    for (int j = 0; j < 64; j++) {
        int grow = it * 64 + j;
        int limit = grow + 1;
        float il = linv[j];
        int col = tid * 4;
        float4 o;
        o.x = (col     < limit) ? __half2float(Ps[j * PST + col])     * il : 0.f;
        o.y = (col + 1 < limit) ? __half2float(Ps[j * PST + col + 1]) * il : 0.f;
        o.z = (col + 2 < limit) ? __half2float(Ps[j * PST + col + 2]) * il : 0.f;
        o.w = (col + 3 < limit) ? __half2float(Ps[j * PST + col + 3]) * il : 0.f;
        *(float4*)(attn + ((size_t)bh * Sz + grow) * Sz + col) = o;
    }
}

// ===================== residual + LayerNorm (vectorized) ====================
__global__ __launch_bounds__(256) void add_ln_kernel(
    const float* __restrict__ x, const float* __restrict__ r,
    const float* __restrict__ g, const float* __restrict__ be,
    float* __restrict__ out, __half* __restrict__ outh)
{
    int row = blockIdx.x;
    const float* xr = x + (size_t)row * Dz;
    const float* rr = r + (size_t)row * Dz;
    float* orow = out + (size_t)row * Dz;
    int tid = threadIdx.x;
    int wrp = tid >> 5, lane = tid & 31;

    float4 xv = *(const float4*)(xr + tid * 4);
    float4 rv = *(const float4*)(rr + tid * 4);
    float4 v;
    v.x = xv.x + rv.x; v.y = xv.y + rv.y;
    v.z = xv.z + rv.z; v.w = xv.w + rv.w;

    float lsum = v.x + v.y + v.z + v.w;
    float lsq  = v.x * v.x + v.y * v.y + v.z * v.z + v.w * v.w;
    #pragma unroll
    for (int s = 16; s > 0; s >>= 1) {
        lsum += __shfl_xor_sync(0xffffffff, lsum, s);
        lsq  += __shfl_xor_sync(0xffffffff, lsq, s);
    }

    __shared__ float s1[8], s2[8];
    if (lane == 0) { s1[wrp] = lsum; s2[wrp] = lsq; }
    __syncthreads();
    if (tid < 32) {
        float a = (lane < 8) ? s1[lane] : 0.f;
        float bsq = (lane < 8) ? s2[lane] : 0.f;
        #pragma unroll
        for (int s = 4; s > 0; s >>= 1) {
            a   += __shfl_xor_sync(0xffffffff, a, s);
            bsq += __shfl_xor_sync(0xffffffff, bsq, s);
        }
        if (lane == 0) { s1[0] = a; s2[0] = bsq; }
    }
    __syncthreads();

    float mean = s1[0] * (1.f / Dz);
    float var  = s2[0] * (1.f / Dz) - mean * mean;
    float inv  = rsqrtf(var + 1e-5f);

    float4 gv = *(const float4*)(g + tid * 4);
    float4 bv = *(const float4*)(be + tid * 4);
    float4 o;
    o.x = (v.x - mean) * inv * gv.x + bv.x;
    o.y = (v.y - mean) * inv * gv.y + bv.y;
    o.z = (v.z - mean) * inv * gv.z + bv.z;
    o.w = (v.w - mean) * inv * gv.w + bv.w;
    *(float4*)(orow + tid * 4) = o;
    if (outh) {
        __half2* oh = (__half2*)(outh + (size_t)row * Dz + tid * 4);
        oh[0] = __floats2half2_rn(o.x, o.y);
        oh[1] = __floats2half2_rn(o.z, o.w);
    }
}

// ===================== host launch ==========================================
extern "C" void kernel_launch(void* const* d_in, const int* in_sizes, int n_in,
                              void* d_out, int out_size)
{
    const float* x    = (const float*)d_in[0];
    const float* Wq   = (const float*)d_in[1];
    const float* bq   = (const float*)d_in[2];
    const float* Wk   = (const float*)d_in[3];
    const float* bk   = (const float*)d_in[4];
    const float* Wv   = (const float*)d_in[5];
    const float* bv   = (const float*)d_in[6];
    const float* Wo   = (const float*)d_in[7];
    const float* bo   = (const float*)d_in[8];
    const float* ln1g = (const float*)d_in[9];
    const float* ln1b = (const float*)d_in[10];
    const float* W1   = (const float*)d_in[11];
    const float* b1   = (const float*)d_in[12];
    const float* W2   = (const float*)d_in[13];
    const float* b2   = (const float*)d_in[14];
    const float* ln2g = (const float*)d_in[15];
    const float* ln2b = (const float*)d_in[16];

    float* out  = (float*)d_out;
    float* y    = out;
    float* attn = out + (size_t)BSz * Dz;

    float *t1, *h, *bqkv;
    __half *xh, *qkvh, *ctxh, *hh, *ffh;
    __half *wqkvh, *woh, *w1h, *w2h;
    cudaGetSymbolAddress((void**)&t1,   g_t1);
    cudaGetSymbolAddress((void**)&h,    g_h);
    cudaGetSymbolAddress((void**)&bqkv, g_bqkv);
    cudaGetSymbolAddress((void**)&xh,   g_xh);
    cudaGetSymbolAddress((void**)&qkvh, g_qkvh);
    cudaGetSymbolAddress((void**)&ctxh, g_ctxh);
    cudaGetSymbolAddress((void**)&hh,   g_hh);
    cudaGetSymbolAddress((void**)&ffh,  g_ffh);
    cudaGetSymbolAddress((void**)&wqkvh, g_wqkvh);
    cudaGetSymbolAddress((void**)&woh,  g_woh);
    cudaGetSymbolAddress((void**)&w1h,  g_w1h);
    cudaGetSymbolAddress((void**)&w2h,  g_w2h);

    cudaFuncSetAttribute(hgemm_kernel,
                         cudaFuncAttributeMaxDynamicSharedMemorySize, GEMM_SMEM);
    cudaFuncSetAttribute(attn_fused_kernel,
                         cudaFuncAttributeMaxDynamicSharedMemorySize, ATT_SMEM);

    static cudaStream_t s2 = nullptr;
    static cudaEvent_t evFork = nullptr, evQKV = nullptr, evJoin = nullptr;
    if (s2 == nullptr) {
        cudaStreamCreateWithFlags(&s2, cudaStreamNonBlocking);
        cudaEventCreateWithFlags(&evFork, cudaEventDisableTiming);
        cudaEventCreateWithFlags(&evQKV, cudaEventDisableTiming);
        cudaEventCreateWithFlags(&evJoin, cudaEventDisableTiming);
    }

    const __half* qh = qkvh;
    const __half* kh = qkvh + Dz;
    const __half* vh = qkvh + 2 * Dz;

    dim3 tDD(Dz / 32, Dz / 32);
    dim3 gQKV(QKVN / GBN, BSz / GBM);   // 12 x 32 = 384 CTAs
    dim3 gDD(Dz / GBN, BSz / GBM);      // 4 x 32 = 128 CTAs
    dim3 gDF(FFz / GBN, BSz / GBM);     // 16 x 32 = 512 CTAs

    Ptr3 wsrc; wsrc.p[0] = Wq; wsrc.p[1] = Wk; wsrc.p[2] = Wv;

    // side stream: QKV weight prep (joins before QKV GEMM), then the
    // later-needed weight transposes (join before Wo GEMM)
    cudaEventRecord(evFork, 0);
    cudaStreamWaitEvent(s2, evFork, 0);
    transpose_qkv_kernel<<<dim3(Dz / 32, Dz / 32, 3), 256, 0, s2>>>(wsrc, wqkvh);
    bias_concat_kernel<<<QKVN / 256, 256, 0, s2>>>(bq, bk, bv, bqkv);
    cudaEventRecord(evQKV, s2);
    transpose_half_kernel<<<dim3(FFz / 32, Dz / 32), 256, 0, s2>>>(W1, w1h, Dz, FFz);
    transpose_half_kernel<<<tDD, 256, 0, s2>>>(Wo, woh, Dz, Dz);
    transpose_half_kernel<<<dim3(Dz / 32, FFz / 32), 256, 0, s2>>>(W2, w2h, FFz, Dz);
    cudaEventRecord(evJoin, s2);

    // main chain: cvt(x) overlaps the QKV weight prep
    cvt_half_kernel<<<(BSz * Dz) / 1024, 256>>>(x, xh);
    cudaStreamWaitEvent(0, evQKV, 0);
    hgemm_kernel<<<gQKV, 512, GEMM_SMEM>>>(xh, wqkvh, bqkv, nullptr, qkvh,
                                           BSz, QKVN, Dz, 0);

    attn_fused_kernel<<<dim3(Sz / 64, BHz), 256, ATT_SMEM>>>(
        qh, kh, vh, QKVN, attn, ctxh);

    cudaStreamWaitEvent(0, evJoin, 0);
    hgemm_kernel<<<gDD, 512, GEMM_SMEM>>>(ctxh, woh, bo, t1, nullptr,
                                          BSz, Dz, Dz, 0);
    add_ln_kernel<<<BSz, 256>>>(x, t1, ln1g, ln1b, h, hh);
    hgemm_kernel<<<gDF, 512, GEMM_SMEM>>>(hh, w1h, b1, nullptr, ffh,
                                          BSz, FFz, Dz, 1);
    hgemm_kernel<<<gDD, 512, GEMM_SMEM>>>(ffh, w2h, b2, t1, nullptr,
                                          BSz, Dz, FFz, 0);
    add_ln_kernel<<<BSz, 256>>>(h, t1, ln2g, ln2b, y, nullptr);
}